// round 1
// baseline (speedup 1.0000x reference)
#include <cuda_runtime.h>
#include <math.h>

#define BB 32
#define NN 12
#define SS 512
#define DD 256
#define AA 96

// Scratch (device globals — no allocation allowed in kernel_launch)
static __device__ float g_E[NN * SS * DD];            // exp(qk)  [n][s][d]
static __device__ float g_qT[NN * DD * SS];           // q transposed [n][d][s]
static __device__ float g_cs_part[8 * NN * DD];       // partial column sums
static __device__ float g_cs[NN * DD];                // colsum[n][d] = sum_s exp(qk)
static __device__ float g_MT[BB * NN * DD * DD];      // (k@value)^T  [bn][f][d]
static __device__ float g_P[BB * NN * DD * DD];       // M@Wv         [bn][d][e]

// ---------------------------------------------------------------------------
// Kernel 1: qk = emb@Wqk + bqk, then exp and the d-softmax (q).
// One block per (n,s) row, 256 threads = D.
// Stores E = exp(qk) (for the s-softmax, normalized later via colsum)
// and qT[n][d][s] = exp(qk)/rowsum (transposed for the TN GEMM3).
// ---------------------------------------------------------------------------
__global__ void qk_kernel(const float* __restrict__ emb,
                          const float* __restrict__ Wqk,
                          const float* __restrict__ bqk)
{
    int ns = blockIdx.x;              // 0 .. N*S-1
    int n = ns / SS;
    int s = ns % SS;
    int d = threadIdx.x;              // 0 .. 255

    __shared__ float se[AA];
    __shared__ float red[256];

    if (d < AA) se[d] = emb[(size_t)ns * AA + d];
    __syncthreads();

    float acc = bqk[d];
#pragma unroll 8
    for (int a = 0; a < AA; ++a)
        acc = fmaf(se[a], Wqk[a * DD + d], acc);

    // qk values are ~N(0,1): exp without max-subtraction is numerically safe
    float e = expf(acc);

    red[d] = e;
    __syncthreads();
#pragma unroll
    for (int off = 128; off > 0; off >>= 1) {
        if (d < off) red[d] += red[d + off];
        __syncthreads();
    }
    float inv = 1.0f / red[0];

    g_qT[((size_t)n * DD + d) * SS + s] = e * inv;   // q transposed
    g_E[(size_t)ns * DD + d] = e;                    // raw exp for k-softmax
}

// ---------------------------------------------------------------------------
// Column sums over s of E (denominator of the s-softmax), two deterministic
// stages (no float atomics).
// ---------------------------------------------------------------------------
__global__ void colsum_part_kernel()
{
    int n = blockIdx.x >> 3;
    int c = blockIdx.x & 7;           // s-chunk 0..7 (64 rows each)
    int d = threadIdx.x;
    float acc = 0.0f;
    int s0 = c * 64;
#pragma unroll 4
    for (int s = s0; s < s0 + 64; ++s)
        acc += g_E[((size_t)n * SS + s) * DD + d];
    g_cs_part[((size_t)c * NN + n) * DD + d] = acc;
}

__global__ void colsum_final_kernel()
{
    int n = blockIdx.x;
    int d = threadIdx.x;
    float acc = 0.0f;
#pragma unroll
    for (int c = 0; c < 8; ++c)
        acc += g_cs_part[((size_t)c * NN + n) * DD + d];
    g_cs[n * DD + d] = acc;
}

// ---------------------------------------------------------------------------
// Batched TN SGEMM: C[m,n] = (sum_k A[k*lda+m] * B[k*ldb+n]) (*1/scale[n]) (+bias[n])
// BM=BN=128, BK=16, 256 threads, 8x8 microtile, packed fma.rn.f32x2 (2 FMA/inst).
// All problem dims divide the tiles exactly -> no bounds checks.
// Batch: z = blockIdx.z; operand offset = (mod ? z%mod : z) * stride.
// ---------------------------------------------------------------------------
__global__ __launch_bounds__(256, 2)
void sgemm_tn(const float* __restrict__ Ag, const float* __restrict__ Bg,
              float* __restrict__ Cg,
              int K, int lda, int ldb, int ldc,
              long aStride, int aMod,
              long bStride, int bMod,
              long cStride,
              const float* __restrict__ scaleBase, int scaleMod,
              const float* __restrict__ bias)
{
    const int BM = 128, BN = 128, BK = 16;
    __shared__ __align__(16) float As[2][BK][BM];
    __shared__ __align__(16) float Bs[2][BK][BN];

    int z = blockIdx.z;
    const float* A  = Ag + (long)(aMod ? (z % aMod) : z) * aStride;
    const float* Bp = Bg + (long)(bMod ? (z % bMod) : z) * bStride;
    float* C = Cg + (long)z * cStride;

    int tid = threadIdx.x;
    int tm = tid >> 4;                // 0..15
    int tn = tid & 15;                // 0..15
    int m0 = blockIdx.y * BM;
    int n0 = blockIdx.x * BN;

    int lrow = tid >> 4;              // k-row within tile
    int lcol = (tid & 15) << 3;       // 8-float column group

    const float* aLoad = A  + (long)lrow * lda + m0 + lcol;
    const float* bLoad = Bp + (long)lrow * ldb + n0 + lcol;
    long aStep = (long)BK * lda;
    long bStep = (long)BK * ldb;

    float4 ra0 = *(const float4*)(aLoad);
    float4 ra1 = *(const float4*)(aLoad + 4);
    float4 rb0 = *(const float4*)(bLoad);
    float4 rb1 = *(const float4*)(bLoad + 4);

    *(float4*)&As[0][lrow][lcol]     = ra0;
    *(float4*)&As[0][lrow][lcol + 4] = ra1;
    *(float4*)&Bs[0][lrow][lcol]     = rb0;
    *(float4*)&Bs[0][lrow][lcol + 4] = rb1;
    __syncthreads();

    unsigned long long acc[8][4];
#pragma unroll
    for (int i = 0; i < 8; ++i)
#pragma unroll
        for (int j = 0; j < 4; ++j) acc[i][j] = 0ULL;

    int KT = K / BK;
    for (int kt = 0; kt < KT; ++kt) {
        int buf = kt & 1;
        bool more = (kt + 1 < KT);
        if (more) {
            const float* ap = aLoad + (long)(kt + 1) * aStep;
            const float* bp = bLoad + (long)(kt + 1) * bStep;
            ra0 = *(const float4*)(ap);
            ra1 = *(const float4*)(ap + 4);
            rb0 = *(const float4*)(bp);
            rb1 = *(const float4*)(bp + 4);
        }
#pragma unroll
        for (int k = 0; k < BK; ++k) {
            float4 a0 = *(const float4*)&As[buf][k][tm << 3];
            float4 a1 = *(const float4*)&As[buf][k][(tm << 3) + 4];
            ulonglong2 b01 = *(const ulonglong2*)&Bs[buf][k][tn << 3];
            ulonglong2 b23 = *(const ulonglong2*)&Bs[buf][k][(tn << 3) + 4];
            unsigned long long bb0 = b01.x, bb1 = b01.y, bb2 = b23.x, bb3 = b23.y;
            float av[8] = {a0.x, a0.y, a0.z, a0.w, a1.x, a1.y, a1.z, a1.w};
#pragma unroll
            for (int i = 0; i < 8; ++i) {
                unsigned int au = __float_as_uint(av[i]);
                unsigned long long aa;
                asm("mov.b64 %0, {%1, %2};" : "=l"(aa) : "r"(au), "r"(au));
                asm("fma.rn.f32x2 %0, %1, %2, %0;" : "+l"(acc[i][0]) : "l"(aa), "l"(bb0));
                asm("fma.rn.f32x2 %0, %1, %2, %0;" : "+l"(acc[i][1]) : "l"(aa), "l"(bb1));
                asm("fma.rn.f32x2 %0, %1, %2, %0;" : "+l"(acc[i][2]) : "l"(aa), "l"(bb2));
                asm("fma.rn.f32x2 %0, %1, %2, %0;" : "+l"(acc[i][3]) : "l"(aa), "l"(bb3));
            }
        }
        __syncthreads();
        if (more) {
            int nb = buf ^ 1;
            *(float4*)&As[nb][lrow][lcol]     = ra0;
            *(float4*)&As[nb][lrow][lcol + 4] = ra1;
            *(float4*)&Bs[nb][lrow][lcol]     = rb0;
            *(float4*)&Bs[nb][lrow][lcol + 4] = rb1;
            __syncthreads();
        }
    }

    // Epilogue
    int gm = m0 + (tm << 3);
    int gn = n0 + (tn << 3);
    float sc[8], bi[8];
    bool hasScale = (scaleBase != nullptr);
    bool hasBias  = (bias != nullptr);
    if (hasScale) {
        const float* sp = scaleBase + (long)(scaleMod ? (z % scaleMod) : z) * DD;
#pragma unroll
        for (int j = 0; j < 8; ++j) sc[j] = 1.0f / sp[gn + j];
    }
    if (hasBias) {
#pragma unroll
        for (int j = 0; j < 8; ++j) bi[j] = bias[gn + j];
    }
#pragma unroll
    for (int i = 0; i < 8; ++i) {
        float outv[8];
#pragma unroll
        for (int j = 0; j < 4; ++j) {
            unsigned int lo, hi;
            asm("mov.b64 {%0, %1}, %2;" : "=r"(lo), "=r"(hi) : "l"(acc[i][j]));
            outv[2 * j]     = __uint_as_float(lo);
            outv[2 * j + 1] = __uint_as_float(hi);
        }
        if (hasScale) {
#pragma unroll
            for (int j = 0; j < 8; ++j) outv[j] *= sc[j];
        }
        if (hasBias) {
#pragma unroll
            for (int j = 0; j < 8; ++j) outv[j] += bi[j];
        }
        *(float4*)&C[(long)(gm + i) * ldc + gn]     = make_float4(outv[0], outv[1], outv[2], outv[3]);
        *(float4*)&C[(long)(gm + i) * ldc + gn + 4] = make_float4(outv[4], outv[5], outv[6], outv[7]);
    }
}

// ---------------------------------------------------------------------------
// Launch. Inputs (metadata order): value, emb, Wqk, bqk, Wv, bv. Output fp32.
//   out = q @ (k @ value) @ Wv + bv          (bias folding: row-sums of q,k are 1)
// GEMM1: MT[f,d]  = sum_s value[s,f]*E[s,d] / colsum[d]      (per bn; E,colsum per n)
// GEMM2: P[d,e]   = sum_f MT[f,d]*Wv[f,e]                    (per bn)
// GEMM3: out[s,e] = sum_d qT[d,s]*P[d,e] + bv[e]             (per bn; qT per n)
// ---------------------------------------------------------------------------
extern "C" void kernel_launch(void* const* d_in, const int* in_sizes, int n_in,
                              void* d_out, int out_size)
{
    const float* value = (const float*)d_in[0];
    const float* emb   = (const float*)d_in[1];
    const float* Wqk   = (const float*)d_in[2];
    const float* bqk   = (const float*)d_in[3];
    const float* Wv    = (const float*)d_in[4];
    const float* bv    = (const float*)d_in[5];
    float* out = (float*)d_out;

    void *pE, *pqT, *pcs, *pMT, *pP;
    cudaGetSymbolAddress(&pE,  g_E);
    cudaGetSymbolAddress(&pqT, g_qT);
    cudaGetSymbolAddress(&pcs, g_cs);
    cudaGetSymbolAddress(&pMT, g_MT);
    cudaGetSymbolAddress(&pP,  g_P);

    qk_kernel<<<NN * SS, 256>>>(emb, Wqk, bqk);
    colsum_part_kernel<<<NN * 8, 256>>>();
    colsum_final_kernel<<<NN, 256>>>();

    // GEMM1: M=256(f) N=256(d) K=512(s)
    sgemm_tn<<<dim3(2, 2, BB * NN), 256>>>(
        value, (const float*)pE, (float*)pMT,
        512, DD, DD, DD,
        (long)SS * DD, 0,          // A: value, per bn
        (long)SS * DD, NN,         // B: E, per n
        (long)DD * DD,             // C: MT, per bn
        (const float*)pcs, NN,     // scale: 1/colsum[n][d] over columns
        nullptr);

    // GEMM2: M=256(d) N=256(e) K=256(f)
    sgemm_tn<<<dim3(2, 2, BB * NN), 256>>>(
        (const float*)pMT, Wv, (float*)pP,
        DD, DD, DD, DD,
        (long)DD * DD, 0,          // A: MT per bn
        0L, 0,                     // B: Wv shared
        (long)DD * DD,
        nullptr, 0, nullptr);

    // GEMM3: M=512(s) N=256(e) K=256(d)
    sgemm_tn<<<dim3(2, 4, BB * NN), 256>>>(
        (const float*)pqT, (const float*)pP, out,
        DD, SS, DD, DD,
        (long)DD * SS, NN,         // A: qT per n
        (long)DD * DD, 0,          // B: P per bn
        (long)SS * DD,             // C: out per bn
        nullptr, 0, bv);           // bias bv over columns e
}

// round 4
// speedup vs baseline: 1.4716x; 1.4716x over previous
#include <cuda_runtime.h>
#include <cuda_bf16.h>
#include <cstdint>
#include <math.h>

#define BB 32
#define NN 12
#define SS 512
#define DD 256
#define AA 96

// ---------------- scratch (device globals) -----------------------------------
static __device__ float g_q[NN * SS * DD];                  // q softmax [n][s][d]
static __device__ float g_ET[NN * DD * SS];                 // exp(qk)^T [n][d][s]
static __device__ float g_cs[NN * DD];                      // colsum over s
static __device__ float g_kv[(size_t)BB * NN * DD * DD];    // kv [bn][d][e]
static __device__ float g_P[(size_t)BB * NN * DD * DD];     // P  [bn][d][e]

// ---------------- helpers ----------------------------------------------------
__device__ __forceinline__ uint32_t smem_u32(const void* p) {
    uint32_t a;
    asm("{ .reg .u64 t; cvta.to.shared.u64 t, %1; cvt.u32.u64 %0, t; }" : "=r"(a) : "l"(p));
    return a;
}
__device__ __forceinline__ void ldsm4(uint32_t* r, uint32_t a) {
    asm volatile("ldmatrix.sync.aligned.m8n8.x4.shared.b16 {%0,%1,%2,%3}, [%4];"
                 : "=r"(r[0]), "=r"(r[1]), "=r"(r[2]), "=r"(r[3]) : "r"(a));
}
__device__ __forceinline__ void ldsm4t(uint32_t* r, uint32_t a) {
    asm volatile("ldmatrix.sync.aligned.m8n8.x4.trans.shared.b16 {%0,%1,%2,%3}, [%4];"
                 : "=r"(r[0]), "=r"(r[1]), "=r"(r[2]), "=r"(r[3]) : "r"(a));
}
__device__ __forceinline__ void mma16816(float* c, const uint32_t* a, const uint32_t* b) {
    asm volatile("mma.sync.aligned.m16n8k16.row.col.f32.bf16.bf16.f32 "
                 "{%0,%1,%2,%3}, {%4,%5,%6,%7}, {%8,%9}, {%0,%1,%2,%3};"
                 : "+f"(c[0]), "+f"(c[1]), "+f"(c[2]), "+f"(c[3])
                 : "r"(a[0]), "r"(a[1]), "r"(a[2]), "r"(a[3]), "r"(b[0]), "r"(b[1]));
}
// split fp32 -> (hi, lo) bf16 pairs packed as uint32 (low half = first elem)
__device__ __forceinline__ void split2(float x, float y, uint32_t& h, uint32_t& l) {
    __nv_bfloat162 hv;
    hv.x = __float2bfloat16(x);
    hv.y = __float2bfloat16(y);
    __nv_bfloat162 lv;
    lv.x = __float2bfloat16(x - __bfloat162float(hv.x));
    lv.y = __float2bfloat16(y - __bfloat162float(hv.y));
    h = *(uint32_t*)&hv;
    l = *(uint32_t*)&lv;
}

// ---------------- small kernels ----------------------------------------------
__global__ void qk_kernel(const float* __restrict__ emb,
                          const float* __restrict__ Wqk,
                          const float* __restrict__ bqk)
{
    int ns = blockIdx.x;
    int n = ns / SS;
    int s = ns % SS;
    int d = threadIdx.x;

    __shared__ float se[AA];
    __shared__ float red[256];

    if (d < AA) se[d] = emb[(size_t)ns * AA + d];
    __syncthreads();

    float acc = bqk[d];
#pragma unroll 8
    for (int a = 0; a < AA; ++a)
        acc = fmaf(se[a], Wqk[a * DD + d], acc);

    float e = expf(acc);
    red[d] = e;
    __syncthreads();
#pragma unroll
    for (int off = 128; off > 0; off >>= 1) {
        if (d < off) red[d] += red[d + off];
        __syncthreads();
    }
    float inv = 1.0f / red[0];

    g_q[(size_t)ns * DD + d] = e * inv;
    g_ET[((size_t)n * DD + d) * SS + s] = e;
}

__global__ void colsum_kernel()
{
    int r = blockIdx.x * 8 + (threadIdx.x >> 5);
    int l = threadIdx.x & 31;
    const float4* p = (const float4*)(g_ET + (size_t)r * SS);
    float4 a = p[l], b = p[l + 32], c = p[l + 64], d4 = p[l + 96];
    float s = a.x + a.y + a.z + a.w + b.x + b.y + b.z + b.w
            + c.x + c.y + c.z + c.w + d4.x + d4.y + d4.z + d4.w;
#pragma unroll
    for (int off = 16; off > 0; off >>= 1) s += __shfl_xor_sync(0xffffffff, s, off);
    if (l == 0) g_cs[r] = s;
}

// ---------------- warp-MMA bf16-split batched GEMM ---------------------------
// C[m,n] = sum_k A[m,k] * B[k,n]      (A: [M,K] row-major; B: [K,N] row-major)
// epilogue: optional row scale 1/scale[m], optional col bias[n].
// bf16 split, 3 passes: ah*bh + al*bh + ah*bl, fp32 accumulate.
#define A_STR 80     // 32 bf16 (64B) + 16B pad  -> conflict-free ldmatrix
#define B_STR 272    // 128 bf16 (256B) + 16B pad
#define SM_AH 0
#define SM_AL 10240
#define SM_BH 20480
#define SM_BL 29184
#define SM_TOT 37888

__global__ __launch_bounds__(256)
void gemm_mma(const float* __restrict__ Ag, const float* __restrict__ Bg,
              float* __restrict__ Cg, int K, int lda, int ldb, int ldc,
              long aStride, int aMod, long bStride, int bMod, long cStride,
              const float* __restrict__ scaleBase, int scaleMod,
              const float* __restrict__ bias)
{
    __shared__ __align__(16) char smem[SM_TOT];

    int z = blockIdx.z;
    const float* A = Ag + (long)(aMod ? (z % aMod) : z) * aStride;
    const float* B = Bg + (long)(bMod ? (z % bMod) : z) * bStride;
    float* C = Cg + (long)z * cStride;
    int m0 = blockIdx.y * 128, n0 = blockIdx.x * 128;

    int tid = threadIdx.x, lane = tid & 31, wid = tid >> 5;
    int wm = wid >> 1, wn = wid & 1;       // warp tile: 32(M) x 64(N)

    // ---- global load mapping (per 128x32 A-chunk, 32x128 B-chunk) ----
    int arow = tid >> 1, akb = (tid & 1) * 16;   // A: row m, 16 k-floats
    int brow = tid >> 3, bnb = (tid & 7) * 16;   // B: row k, 16 n-floats
    const float* aPtr = A + (long)(m0 + arow) * lda + akb;
    const float* bPtr = B + (long)brow * ldb + n0 + bnb;

    uint32_t sb = smem_u32(smem);
    uint32_t aStoreH = sb + SM_AH + arow * A_STR + akb * 2;
    uint32_t aStoreL = sb + SM_AL + arow * A_STR + akb * 2;
    uint32_t bStoreH = sb + SM_BH + brow * B_STR + bnb * 2;
    uint32_t bStoreL = sb + SM_BL + brow * B_STR + bnb * 2;

    // ---- fragment addresses ----
    uint32_t aAdH[2], aAdL[2], bAdH[4], bAdL[4];
#pragma unroll
    for (int t = 0; t < 2; ++t) {
        uint32_t off = (uint32_t)((wm * 32 + t * 16 + (lane & 15)) * A_STR + (lane >> 4) * 16);
        aAdH[t] = sb + SM_AH + off;
        aAdL[t] = sb + SM_AL + off;
    }
#pragma unroll
    for (int p = 0; p < 4; ++p) {
        uint32_t off = (uint32_t)((lane & 15) * B_STR + (wn * 64 + p * 16 + (lane >> 4) * 8) * 2);
        bAdH[p] = sb + SM_BH + off;
        bAdL[p] = sb + SM_BL + off;
    }

    float acc[2][8][4];
#pragma unroll
    for (int t = 0; t < 2; ++t)
#pragma unroll
        for (int nt = 0; nt < 8; ++nt)
#pragma unroll
            for (int j = 0; j < 4; ++j) acc[t][nt][j] = 0.0f;

    // preload chunk 0
    float4 ra[4], rb[4];
#pragma unroll
    for (int j = 0; j < 4; ++j) {
        ra[j] = *(const float4*)(aPtr + j * 4);
        rb[j] = *(const float4*)(bPtr + j * 4);
    }

    int KT = K / 32;
    for (int kc = 0; kc < KT; ++kc) {
        // convert + store to SMEM (hi/lo split)
        {
            uint32_t h[4], l[4];
#pragma unroll
            for (int j = 0; j < 2; ++j) {
                split2(ra[2 * j].x, ra[2 * j].y, h[0], l[0]);
                split2(ra[2 * j].z, ra[2 * j].w, h[1], l[1]);
                split2(ra[2 * j + 1].x, ra[2 * j + 1].y, h[2], l[2]);
                split2(ra[2 * j + 1].z, ra[2 * j + 1].w, h[3], l[3]);
                *(uint4*)(smem + (aStoreH - sb) + j * 16) = make_uint4(h[0], h[1], h[2], h[3]);
                *(uint4*)(smem + (aStoreL - sb) + j * 16) = make_uint4(l[0], l[1], l[2], l[3]);
            }
#pragma unroll
            for (int j = 0; j < 2; ++j) {
                split2(rb[2 * j].x, rb[2 * j].y, h[0], l[0]);
                split2(rb[2 * j].z, rb[2 * j].w, h[1], l[1]);
                split2(rb[2 * j + 1].x, rb[2 * j + 1].y, h[2], l[2]);
                split2(rb[2 * j + 1].z, rb[2 * j + 1].w, h[3], l[3]);
                *(uint4*)(smem + (bStoreH - sb) + j * 16) = make_uint4(h[0], h[1], h[2], h[3]);
                *(uint4*)(smem + (bStoreL - sb) + j * 16) = make_uint4(l[0], l[1], l[2], l[3]);
            }
        }
        __syncthreads();

        // prefetch next chunk (overlaps MMA loop)
        if (kc + 1 < KT) {
            aPtr += 32;
            bPtr += 32 * (long)ldb;
#pragma unroll
            for (int j = 0; j < 4; ++j) {
                ra[j] = *(const float4*)(aPtr + j * 4);
                rb[j] = *(const float4*)(bPtr + j * 4);
            }
        }

        // MMA: two k16 steps
#pragma unroll
        for (int kk = 0; kk < 2; ++kk) {
            uint32_t ah[2][4], al[2][4], bf[4][4];
#pragma unroll
            for (int t = 0; t < 2; ++t) {
                ldsm4(ah[t], aAdH[t] + kk * 32);
                ldsm4(al[t], aAdL[t] + kk * 32);
            }
#pragma unroll
            for (int p = 0; p < 4; ++p) ldsm4t(bf[p], bAdH[p] + kk * 16 * B_STR);
#pragma unroll
            for (int t = 0; t < 2; ++t)
#pragma unroll
                for (int nt = 0; nt < 8; ++nt)
                    mma16816(acc[t][nt], ah[t], &bf[nt >> 1][(nt & 1) * 2]);
#pragma unroll
            for (int t = 0; t < 2; ++t)
#pragma unroll
                for (int nt = 0; nt < 8; ++nt)
                    mma16816(acc[t][nt], al[t], &bf[nt >> 1][(nt & 1) * 2]);
#pragma unroll
            for (int p = 0; p < 4; ++p) ldsm4t(bf[p], bAdL[p] + kk * 16 * B_STR);
#pragma unroll
            for (int t = 0; t < 2; ++t)
#pragma unroll
                for (int nt = 0; nt < 8; ++nt)
                    mma16816(acc[t][nt], ah[t], &bf[nt >> 1][(nt & 1) * 2]);
        }
        __syncthreads();
    }

    // ---- epilogue ----
    const float* sp = scaleBase ? scaleBase + (long)(scaleMod ? (z % scaleMod) : z) * DD : nullptr;
#pragma unroll
    for (int t = 0; t < 2; ++t) {
        int row = m0 + wm * 32 + t * 16 + (lane >> 2);
        float s0 = 1.0f, s1 = 1.0f;
        if (sp) { s0 = 1.0f / sp[row]; s1 = 1.0f / sp[row + 8]; }
#pragma unroll
        for (int nt = 0; nt < 8; ++nt) {
            int col = n0 + wn * 64 + nt * 8 + (lane & 3) * 2;
            float bx = 0.0f, by = 0.0f;
            if (bias) { float2 bb = *(const float2*)(bias + col); bx = bb.x; by = bb.y; }
            float2 v0 = make_float2(acc[t][nt][0] * s0 + bx, acc[t][nt][1] * s0 + by);
            float2 v1 = make_float2(acc[t][nt][2] * s1 + bx, acc[t][nt][3] * s1 + by);
            *(float2*)&C[(long)row * ldc + col] = v0;
            *(float2*)&C[(long)(row + 8) * ldc + col] = v1;
        }
    }
}

// ---------------- launch -----------------------------------------------------
extern "C" void kernel_launch(void* const* d_in, const int* in_sizes, int n_in,
                              void* d_out, int out_size)
{
    const float* value = (const float*)d_in[0];
    const float* emb   = (const float*)d_in[1];
    const float* Wqk   = (const float*)d_in[2];
    const float* bqk   = (const float*)d_in[3];
    const float* Wv    = (const float*)d_in[4];
    const float* bv    = (const float*)d_in[5];
    float* out = (float*)d_out;

    void *pq, *pET, *pcs, *pkv, *pP;
    cudaGetSymbolAddress(&pq, g_q);
    cudaGetSymbolAddress(&pET, g_ET);
    cudaGetSymbolAddress(&pcs, g_cs);
    cudaGetSymbolAddress(&pkv, g_kv);
    cudaGetSymbolAddress(&pP, g_P);

    qk_kernel<<<NN * SS, 256>>>(emb, Wqk, bqk);
    colsum_kernel<<<NN * DD / 8, 256>>>();

    // GEMM1: kv[d,e] = (sum_s ET[d,s] * value[s,e]) / colsum[d]
    gemm_mma<<<dim3(2, 2, BB * NN), 256>>>(
        (const float*)pET, value, (float*)pkv,
        SS, SS, DD, DD,
        (long)DD * SS, NN,          // A: ET per n
        (long)SS * DD, 0,           // B: value per bn
        (long)DD * DD,
        (const float*)pcs, NN, nullptr);

    // GEMM2: P[d,e] = sum_f kv[d,f] * Wv[f,e]
    gemm_mma<<<dim3(2, 2, BB * NN), 256>>>(
        (const float*)pkv, Wv, (float*)pP,
        DD, DD, DD, DD,
        (long)DD * DD, 0,           // A: kv per bn
        0L, 0,                      // B: Wv shared
        (long)DD * DD,
        nullptr, 0, nullptr);

    // GEMM3: out[s,e] = sum_d q[s,d] * P[d,e] + bv[e]
    gemm_mma<<<dim3(2, 4, BB * NN), 256>>>(
        (const float*)pq, (const float*)pP, out,
        DD, DD, DD, DD,
        (long)SS * DD, NN,          // A: q per n
        (long)DD * DD, 0,           // B: P per bn
        (long)SS * DD,
        nullptr, 0, bv);
}

// round 5
// speedup vs baseline: 1.7047x; 1.1584x over previous
#include <cuda_runtime.h>
#include <cuda_bf16.h>
#include <cstdint>
#include <math.h>

#define BB 32
#define NN 12
#define SS 512
#define DD 256
#define AA 96

// ---------------- scratch (device globals) -----------------------------------
static __device__ float g_q[NN * SS * DD];                  // q softmax [n][s][d]
static __device__ float g_ET[NN * DD * SS];                 // exp(qk)^T [n][d][s]
static __device__ float g_cs[NN * DD];                      // colsum over s
static __device__ float g_kv[(size_t)BB * NN * DD * DD];    // kv [bn][d][e]
static __device__ float g_P[(size_t)BB * NN * DD * DD];     // P  [bn][d][e]

// ---------------- helpers ----------------------------------------------------
__device__ __forceinline__ uint32_t smem_u32(const void* p) {
    uint32_t a;
    asm("{ .reg .u64 t; cvta.to.shared.u64 t, %1; cvt.u32.u64 %0, t; }" : "=r"(a) : "l"(p));
    return a;
}
__device__ __forceinline__ void ldsm4(uint32_t* r, uint32_t a) {
    asm volatile("ldmatrix.sync.aligned.m8n8.x4.shared.b16 {%0,%1,%2,%3}, [%4];"
                 : "=r"(r[0]), "=r"(r[1]), "=r"(r[2]), "=r"(r[3]) : "r"(a));
}
__device__ __forceinline__ void ldsm4t(uint32_t* r, uint32_t a) {
    asm volatile("ldmatrix.sync.aligned.m8n8.x4.trans.shared.b16 {%0,%1,%2,%3}, [%4];"
                 : "=r"(r[0]), "=r"(r[1]), "=r"(r[2]), "=r"(r[3]) : "r"(a));
}
__device__ __forceinline__ void mma16816(float* c, const uint32_t* a, const uint32_t* b) {
    asm volatile("mma.sync.aligned.m16n8k16.row.col.f32.bf16.bf16.f32 "
                 "{%0,%1,%2,%3}, {%4,%5,%6,%7}, {%8,%9}, {%0,%1,%2,%3};"
                 : "+f"(c[0]), "+f"(c[1]), "+f"(c[2]), "+f"(c[3])
                 : "r"(a[0]), "r"(a[1]), "r"(a[2]), "r"(a[3]), "r"(b[0]), "r"(b[1]));
}
// split fp32 -> (hi, lo) bf16 pairs packed as uint32 (low half = first elem)
__device__ __forceinline__ void split2(float x, float y, uint32_t& h, uint32_t& l) {
    __nv_bfloat162 hv;
    hv.x = __float2bfloat16(x);
    hv.y = __float2bfloat16(y);
    __nv_bfloat162 lv;
    lv.x = __float2bfloat16(x - __bfloat162float(hv.x));
    lv.y = __float2bfloat16(y - __bfloat162float(hv.y));
    h = *(uint32_t*)&hv;
    l = *(uint32_t*)&lv;
}

// ---------------- small kernels ----------------------------------------------
// 4 s-rows per block: 4x Wqk reuse, float4 reduction, 16B ET stores.
#define SROWS 4
__global__ void qk_kernel(const float* __restrict__ emb,
                          const float* __restrict__ Wqk,
                          const float* __restrict__ bqk)
{
    int blk = blockIdx.x;                      // 0 .. NN*SS/SROWS-1
    int n = blk / (SS / SROWS);
    int s0 = (blk % (SS / SROWS)) * SROWS;
    int d = threadIdx.x;

    __shared__ float se[SROWS][AA];
    __shared__ float4 red[256];

    if (d < AA) {
#pragma unroll
        for (int i = 0; i < SROWS; ++i)
            se[i][d] = emb[((size_t)(n * SS + s0 + i)) * AA + d];
    }
    __syncthreads();

    float b0 = bqk[d];
    float a0 = b0, a1 = b0, a2 = b0, a3 = b0;
#pragma unroll 4
    for (int a = 0; a < AA; ++a) {
        float w = Wqk[a * DD + d];
        a0 = fmaf(se[0][a], w, a0);
        a1 = fmaf(se[1][a], w, a1);
        a2 = fmaf(se[2][a], w, a2);
        a3 = fmaf(se[3][a], w, a3);
    }
    float e0 = expf(a0), e1 = expf(a1), e2 = expf(a2), e3 = expf(a3);

    red[d] = make_float4(e0, e1, e2, e3);
    __syncthreads();
#pragma unroll
    for (int off = 128; off > 0; off >>= 1) {
        if (d < off) {
            float4 x = red[d], y = red[d + off];
            red[d] = make_float4(x.x + y.x, x.y + y.y, x.z + y.z, x.w + y.w);
        }
        __syncthreads();
    }
    float4 rs = red[0];

    g_q[((size_t)(n * SS + s0 + 0)) * DD + d] = e0 / rs.x;
    g_q[((size_t)(n * SS + s0 + 1)) * DD + d] = e1 / rs.y;
    g_q[((size_t)(n * SS + s0 + 2)) * DD + d] = e2 / rs.z;
    g_q[((size_t)(n * SS + s0 + 3)) * DD + d] = e3 / rs.w;
    *(float4*)&g_ET[((size_t)n * DD + d) * SS + s0] = make_float4(e0, e1, e2, e3);
}

__global__ void colsum_kernel()
{
    int r = blockIdx.x * 8 + (threadIdx.x >> 5);
    int l = threadIdx.x & 31;
    const float4* p = (const float4*)(g_ET + (size_t)r * SS);
    float4 a = p[l], b = p[l + 32], c = p[l + 64], d4 = p[l + 96];
    float s = a.x + a.y + a.z + a.w + b.x + b.y + b.z + b.w
            + c.x + c.y + c.z + c.w + d4.x + d4.y + d4.z + d4.w;
#pragma unroll
    for (int off = 16; off > 0; off >>= 1) s += __shfl_xor_sync(0xffffffff, s, off);
    if (l == 0) g_cs[r] = s;
}

// ---------------- warp-MMA bf16-split batched GEMM ---------------------------
// C[m,n] = sum_k A[m,k] * B[k,n]      (A: [M,K] row-major; B: [K,N] row-major)
// bf16 split, 3 passes: ah*bh + al*bh + ah*bl, fp32 accumulate.
// DOUBLE-BUFFERED: one __syncthreads per K-chunk; next-chunk convert/STS issued
// between the two k16 MMA sub-blocks of the current chunk.
#define A_STR 80     // 32 bf16 (64B) + 16B pad  -> conflict-free ldmatrix
#define B_STR 272    // 128 bf16 (256B) + 16B pad
#define SM_AH 0
#define SM_AL 10240
#define SM_BH 20480
#define SM_BL 29184
#define SM_TOT 37888
#define SM_DBL (2 * SM_TOT)

__global__ __launch_bounds__(256)
void gemm_mma(const float* __restrict__ Ag, const float* __restrict__ Bg,
              float* __restrict__ Cg, int K, int lda, int ldb, int ldc,
              long aStride, int aMod, long bStride, int bMod, long cStride,
              const float* __restrict__ scaleBase, int scaleMod,
              const float* __restrict__ bias)
{
    extern __shared__ __align__(16) char smem[];

    int z = blockIdx.z;
    const float* A = Ag + (long)(aMod ? (z % aMod) : z) * aStride;
    const float* B = Bg + (long)(bMod ? (z % bMod) : z) * bStride;
    float* C = Cg + (long)z * cStride;
    int m0 = blockIdx.y * 128, n0 = blockIdx.x * 128;

    int tid = threadIdx.x, lane = tid & 31, wid = tid >> 5;
    int wm = wid >> 1, wn = wid & 1;       // warp tile: 32(M) x 64(N)

    // ---- global load mapping (per 128x32 A-chunk, 32x128 B-chunk) ----
    int arow = tid >> 1, akb = (tid & 1) * 16;   // A: row m, 16 k-floats
    int brow = tid >> 3, bnb = (tid & 7) * 16;   // B: row k, 16 n-floats
    const float* aPtr = A + (long)(m0 + arow) * lda + akb;
    const float* bPtr = B + (long)brow * ldb + n0 + bnb;

    uint32_t sb = smem_u32(smem);
    // byte offsets within one buffer
    uint32_t aOffH = SM_AH + arow * A_STR + akb * 2;
    uint32_t aOffL = SM_AL + arow * A_STR + akb * 2;
    uint32_t bOffH = SM_BH + brow * B_STR + bnb * 2;
    uint32_t bOffL = SM_BL + brow * B_STR + bnb * 2;

    // ---- fragment offsets (within one buffer) ----
    uint32_t aFH[2], aFL[2], bFH[4], bFL[4];
#pragma unroll
    for (int t = 0; t < 2; ++t) {
        uint32_t off = (uint32_t)((wm * 32 + t * 16 + (lane & 15)) * A_STR + (lane >> 4) * 16);
        aFH[t] = SM_AH + off;
        aFL[t] = SM_AL + off;
    }
#pragma unroll
    for (int p = 0; p < 4; ++p) {
        uint32_t off = (uint32_t)((lane & 15) * B_STR + (wn * 64 + p * 16 + (lane >> 4) * 8) * 2);
        bFH[p] = SM_BH + off;
        bFL[p] = SM_BL + off;
    }

    float acc[2][8][4];
#pragma unroll
    for (int t = 0; t < 2; ++t)
#pragma unroll
        for (int nt = 0; nt < 8; ++nt)
#pragma unroll
            for (int j = 0; j < 4; ++j) acc[t][nt][j] = 0.0f;

    float4 ra[4], rb[4];

    auto loadChunk = [&]() {
#pragma unroll
        for (int j = 0; j < 4; ++j) {
            ra[j] = *(const float4*)(aPtr + j * 4);
            rb[j] = *(const float4*)(bPtr + j * 4);
        }
    };
    auto storeChunk = [&](uint32_t bufOff) {
        uint32_t h[4], l[4];
#pragma unroll
        for (int j = 0; j < 2; ++j) {
            split2(ra[2 * j].x, ra[2 * j].y, h[0], l[0]);
            split2(ra[2 * j].z, ra[2 * j].w, h[1], l[1]);
            split2(ra[2 * j + 1].x, ra[2 * j + 1].y, h[2], l[2]);
            split2(ra[2 * j + 1].z, ra[2 * j + 1].w, h[3], l[3]);
            *(uint4*)(smem + bufOff + aOffH + j * 16) = make_uint4(h[0], h[1], h[2], h[3]);
            *(uint4*)(smem + bufOff + aOffL + j * 16) = make_uint4(l[0], l[1], l[2], l[3]);
        }
#pragma unroll
        for (int j = 0; j < 2; ++j) {
            split2(rb[2 * j].x, rb[2 * j].y, h[0], l[0]);
            split2(rb[2 * j].z, rb[2 * j].w, h[1], l[1]);
            split2(rb[2 * j + 1].x, rb[2 * j + 1].y, h[2], l[2]);
            split2(rb[2 * j + 1].z, rb[2 * j + 1].w, h[3], l[3]);
            *(uint4*)(smem + bufOff + bOffH + j * 16) = make_uint4(h[0], h[1], h[2], h[3]);
            *(uint4*)(smem + bufOff + bOffL + j * 16) = make_uint4(l[0], l[1], l[2], l[3]);
        }
    };
    auto mmaStep = [&](int kk, uint32_t bufOff) {
        uint32_t ah[2][4], al[2][4], bf[4][4];
#pragma unroll
        for (int t = 0; t < 2; ++t) {
            ldsm4(ah[t], sb + bufOff + aFH[t] + kk * 32);
            ldsm4(al[t], sb + bufOff + aFL[t] + kk * 32);
        }
#pragma unroll
        for (int p = 0; p < 4; ++p) ldsm4t(bf[p], sb + bufOff + bFH[p] + kk * 16 * B_STR);
#pragma unroll
        for (int t = 0; t < 2; ++t)
#pragma unroll
            for (int nt = 0; nt < 8; ++nt)
                mma16816(acc[t][nt], ah[t], &bf[nt >> 1][(nt & 1) * 2]);
#pragma unroll
        for (int t = 0; t < 2; ++t)
#pragma unroll
            for (int nt = 0; nt < 8; ++nt)
                mma16816(acc[t][nt], al[t], &bf[nt >> 1][(nt & 1) * 2]);
#pragma unroll
        for (int p = 0; p < 4; ++p) ldsm4t(bf[p], sb + bufOff + bFL[p] + kk * 16 * B_STR);
#pragma unroll
        for (int t = 0; t < 2; ++t)
#pragma unroll
            for (int nt = 0; nt < 8; ++nt)
                mma16816(acc[t][nt], ah[t], &bf[nt >> 1][(nt & 1) * 2]);
    };

    // prologue: chunk 0 -> buf 0
    loadChunk();
    storeChunk(0);
    __syncthreads();

    int KT = K / 32;
    for (int kc = 0; kc < KT; ++kc) {
        uint32_t curOff = (kc & 1) ? (uint32_t)SM_TOT : 0u;
        uint32_t nxtOff = SM_TOT - curOff;
        bool more = (kc + 1 < KT);
        if (more) {
            aPtr += 32;
            bPtr += 32 * (long)ldb;
            loadChunk();
        }
        mmaStep(0, curOff);          // tensor work...
        if (more) storeChunk(nxtOff); // ...overlapped with next-chunk STS (other buffer)
        mmaStep(1, curOff);
        __syncthreads();             // single barrier per chunk
    }

    // ---- epilogue ----
    const float* sp = scaleBase ? scaleBase + (long)(scaleMod ? (z % scaleMod) : z) * DD : nullptr;
#pragma unroll
    for (int t = 0; t < 2; ++t) {
        int row = m0 + wm * 32 + t * 16 + (lane >> 2);
        float s0 = 1.0f, s1 = 1.0f;
        if (sp) { s0 = 1.0f / sp[row]; s1 = 1.0f / sp[row + 8]; }
#pragma unroll
        for (int nt = 0; nt < 8; ++nt) {
            int col = n0 + wn * 64 + nt * 8 + (lane & 3) * 2;
            float bx = 0.0f, by = 0.0f;
            if (bias) { float2 bb = *(const float2*)(bias + col); bx = bb.x; by = bb.y; }
            float2 v0 = make_float2(acc[t][nt][0] * s0 + bx, acc[t][nt][1] * s0 + by);
            float2 v1 = make_float2(acc[t][nt][2] * s1 + bx, acc[t][nt][3] * s1 + by);
            *(float2*)&C[(long)row * ldc + col] = v0;
            *(float2*)&C[(long)(row + 8) * ldc + col] = v1;
        }
    }
}

// ---------------- launch -----------------------------------------------------
extern "C" void kernel_launch(void* const* d_in, const int* in_sizes, int n_in,
                              void* d_out, int out_size)
{
    const float* value = (const float*)d_in[0];
    const float* emb   = (const float*)d_in[1];
    const float* Wqk   = (const float*)d_in[2];
    const float* bqk   = (const float*)d_in[3];
    const float* Wv    = (const float*)d_in[4];
    const float* bv    = (const float*)d_in[5];
    float* out = (float*)d_out;

    void *pq, *pET, *pcs, *pkv, *pP;
    cudaGetSymbolAddress(&pq, g_q);
    cudaGetSymbolAddress(&pET, g_ET);
    cudaGetSymbolAddress(&pcs, g_cs);
    cudaGetSymbolAddress(&pkv, g_kv);
    cudaGetSymbolAddress(&pP, g_P);

    static int smemSet = 0;
    if (!smemSet) {
        cudaFuncSetAttribute(gemm_mma, cudaFuncAttributeMaxDynamicSharedMemorySize, SM_DBL);
        smemSet = 1;
    }

    qk_kernel<<<NN * SS / SROWS, 256>>>(emb, Wqk, bqk);
    colsum_kernel<<<NN * DD / 8, 256>>>();

    // GEMM1: kv[d,e] = (sum_s ET[d,s] * value[s,e]) / colsum[d]
    gemm_mma<<<dim3(2, 2, BB * NN), 256, SM_DBL>>>(
        (const float*)pET, value, (float*)pkv,
        SS, SS, DD, DD,
        (long)DD * SS, NN,          // A: ET per n
        (long)SS * DD, 0,           // B: value per bn
        (long)DD * DD,
        (const float*)pcs, NN, nullptr);

    // GEMM2: P[d,e] = sum_f kv[d,f] * Wv[f,e]
    gemm_mma<<<dim3(2, 2, BB * NN), 256, SM_DBL>>>(
        (const float*)pkv, Wv, (float*)pP,
        DD, DD, DD, DD,
        (long)DD * DD, 0,           // A: kv per bn
        0L, 0,                      // B: Wv shared
        (long)DD * DD,
        nullptr, 0, nullptr);

    // GEMM3: out[s,e] = sum_d q[s,d] * P[d,e] + bv[e]
    gemm_mma<<<dim3(2, 4, BB * NN), 256, SM_DBL>>>(
        (const float*)pq, (const float*)pP, out,
        DD, DD, DD, DD,
        (long)SS * DD, NN,          // A: q per n
        (long)DD * DD, 0,           // B: P per bn
        (long)SS * DD,
        nullptr, 0, bv);
}

// round 6
// speedup vs baseline: 2.1285x; 1.2486x over previous
#include <cuda_runtime.h>
#include <cuda_bf16.h>
#include <cstdint>
#include <math.h>

#define BB 32
#define NN 12
#define SS 512
#define DD 256
#define AA 96

// ---------------- scratch (device globals) -----------------------------------
static __device__ float g_q[NN * SS * DD];                  // q softmax [n][s][d]
static __device__ float g_ET[NN * DD * SS];                 // exp(qk)^T [n][d][s]
static __device__ float g_cs[NN * DD];                      // colsum over s
static __device__ float g_kv[(size_t)BB * NN * DD * DD];    // kv [bn][d][e]
static __device__ float g_P[(size_t)BB * NN * DD * DD];     // P  [bn][d][e]

// ---------------- helpers ----------------------------------------------------
__device__ __forceinline__ uint32_t smem_u32(const void* p) {
    uint32_t a;
    asm("{ .reg .u64 t; cvta.to.shared.u64 t, %1; cvt.u32.u64 %0, t; }" : "=r"(a) : "l"(p));
    return a;
}
__device__ __forceinline__ void ldsm4(uint32_t* r, uint32_t a) {
    asm volatile("ldmatrix.sync.aligned.m8n8.x4.shared.b16 {%0,%1,%2,%3}, [%4];"
                 : "=r"(r[0]), "=r"(r[1]), "=r"(r[2]), "=r"(r[3]) : "r"(a));
}
__device__ __forceinline__ void ldsm4t(uint32_t* r, uint32_t a) {
    asm volatile("ldmatrix.sync.aligned.m8n8.x4.trans.shared.b16 {%0,%1,%2,%3}, [%4];"
                 : "=r"(r[0]), "=r"(r[1]), "=r"(r[2]), "=r"(r[3]) : "r"(a));
}
__device__ __forceinline__ void mma16816(float* c, const uint32_t* a, const uint32_t* b) {
    asm volatile("mma.sync.aligned.m16n8k16.row.col.f32.bf16.bf16.f32 "
                 "{%0,%1,%2,%3}, {%4,%5,%6,%7}, {%8,%9}, {%0,%1,%2,%3};"
                 : "+f"(c[0]), "+f"(c[1]), "+f"(c[2]), "+f"(c[3])
                 : "r"(a[0]), "r"(a[1]), "r"(a[2]), "r"(a[3]), "r"(b[0]), "r"(b[1]));
}
// split fp32 -> (hi, lo) bf16 pairs packed as uint32 (low half = first elem)
__device__ __forceinline__ void split2(float x, float y, uint32_t& h, uint32_t& l) {
    __nv_bfloat162 hv;
    hv.x = __float2bfloat16(x);
    hv.y = __float2bfloat16(y);
    __nv_bfloat162 lv;
    lv.x = __float2bfloat16(x - __bfloat162float(hv.x));
    lv.y = __float2bfloat16(y - __bfloat162float(hv.y));
    h = *(uint32_t*)&hv;
    l = *(uint32_t*)&lv;
}

// ---------------- small kernels ----------------------------------------------
#define SROWS 4
__global__ void qk_kernel(const float* __restrict__ emb,
                          const float* __restrict__ Wqk,
                          const float* __restrict__ bqk)
{
    int blk = blockIdx.x;
    int n = blk / (SS / SROWS);
    int s0 = (blk % (SS / SROWS)) * SROWS;
    int d = threadIdx.x;

    __shared__ float se[SROWS][AA];
    __shared__ float4 red[256];

    if (d < AA) {
#pragma unroll
        for (int i = 0; i < SROWS; ++i)
            se[i][d] = emb[((size_t)(n * SS + s0 + i)) * AA + d];
    }
    __syncthreads();

    float b0 = bqk[d];
    float a0 = b0, a1 = b0, a2 = b0, a3 = b0;
#pragma unroll 4
    for (int a = 0; a < AA; ++a) {
        float w = Wqk[a * DD + d];
        a0 = fmaf(se[0][a], w, a0);
        a1 = fmaf(se[1][a], w, a1);
        a2 = fmaf(se[2][a], w, a2);
        a3 = fmaf(se[3][a], w, a3);
    }
    float e0 = expf(a0), e1 = expf(a1), e2 = expf(a2), e3 = expf(a3);

    red[d] = make_float4(e0, e1, e2, e3);
    __syncthreads();
#pragma unroll
    for (int off = 128; off > 0; off >>= 1) {
        if (d < off) {
            float4 x = red[d], y = red[d + off];
            red[d] = make_float4(x.x + y.x, x.y + y.y, x.z + y.z, x.w + y.w);
        }
        __syncthreads();
    }
    float4 rs = red[0];

    g_q[((size_t)(n * SS + s0 + 0)) * DD + d] = e0 / rs.x;
    g_q[((size_t)(n * SS + s0 + 1)) * DD + d] = e1 / rs.y;
    g_q[((size_t)(n * SS + s0 + 2)) * DD + d] = e2 / rs.z;
    g_q[((size_t)(n * SS + s0 + 3)) * DD + d] = e3 / rs.w;
    *(float4*)&g_ET[((size_t)n * DD + d) * SS + s0] = make_float4(e0, e1, e2, e3);
}

__global__ void colsum_kernel()
{
    int r = blockIdx.x * 8 + (threadIdx.x >> 5);
    int l = threadIdx.x & 31;
    const float4* p = (const float4*)(g_ET + (size_t)r * SS);
    float4 a = p[l], b = p[l + 32], c = p[l + 64], d4 = p[l + 96];
    float s = a.x + a.y + a.z + a.w + b.x + b.y + b.z + b.w
            + c.x + c.y + c.z + c.w + d4.x + d4.y + d4.z + d4.w;
#pragma unroll
    for (int off = 16; off > 0; off >>= 1) s += __shfl_xor_sync(0xffffffff, s, off);
    if (l == 0) g_cs[r] = s;
}

// ---------------- warp-MMA bf16-split batched GEMM ---------------------------
// C[m,n] = sum_k A[m,k] * B[k,n]   (A row-major, B row-major; B transposed via ldmatrix)
// bf16 split, 3 passes: ah*bh + al*bh + ah*bl, fp32 accumulate.
// Double-buffered; inline LDG->split->STS between MMA sub-steps; 2 CTAs/SM.
#define A_STR 80
#define B_STR 272
#define SM_AH 0
#define SM_AL 10240
#define SM_BH 20480
#define SM_BL 29184
#define SM_TOT 37888
#define SM_DBL (2 * SM_TOT)

__global__ __launch_bounds__(256, 2)
void gemm_mma(const float* __restrict__ Ag, const float* __restrict__ Bg,
              float* __restrict__ Cg, int K, int lda, int ldb, int ldc,
              long aStride, int aMod, long bStride, int bMod, long cStride,
              const float* __restrict__ scaleBase, int scaleMod,
              const float* __restrict__ bias)
{
    extern __shared__ __align__(16) char smem[];

    int z = blockIdx.z;
    const float* A = Ag + (long)(aMod ? (z % aMod) : z) * aStride;
    const float* B = Bg + (long)(bMod ? (z % bMod) : z) * bStride;
    float* C = Cg + (long)z * cStride;
    int m0 = blockIdx.y * 128, n0 = blockIdx.x * 128;

    int tid = threadIdx.x, lane = tid & 31, wid = tid >> 5;
    int wm = wid >> 1, wn = wid & 1;       // warp tile: 32(M) x 64(N)

    int arow = tid >> 1, akb = (tid & 1) * 16;
    int brow = tid >> 3, bnb = (tid & 7) * 16;
    const float* aPtr = A + (long)(m0 + arow) * lda + akb;
    const float* bPtr = B + (long)brow * ldb + n0 + bnb;

    uint32_t sb = smem_u32(smem);
    uint32_t aOffH = SM_AH + arow * A_STR + akb * 2;
    uint32_t aOffL = SM_AL + arow * A_STR + akb * 2;
    uint32_t bOffH = SM_BH + brow * B_STR + bnb * 2;
    uint32_t bOffL = SM_BL + brow * B_STR + bnb * 2;

    uint32_t aFH[2], aFL[2], bFH[4], bFL[4];
#pragma unroll
    for (int t = 0; t < 2; ++t) {
        uint32_t off = (uint32_t)((wm * 32 + t * 16 + (lane & 15)) * A_STR + (lane >> 4) * 16);
        aFH[t] = SM_AH + off;
        aFL[t] = SM_AL + off;
    }
#pragma unroll
    for (int p = 0; p < 4; ++p) {
        uint32_t off = (uint32_t)((lane & 15) * B_STR + (wn * 64 + p * 16 + (lane >> 4) * 8) * 2);
        bFH[p] = SM_BH + off;
        bFL[p] = SM_BL + off;
    }

    float acc[2][8][4];
#pragma unroll
    for (int t = 0; t < 2; ++t)
#pragma unroll
        for (int nt = 0; nt < 8; ++nt)
#pragma unroll
            for (int j = 0; j < 4; ++j) acc[t][nt][j] = 0.0f;

    // inline LDG -> split -> STS (transient registers only)
    auto loadStore = [&](int kc, uint32_t bufOff) {
        const float* ap = aPtr + kc * 32;
        const float* bp = bPtr + (long)kc * 32 * ldb;
        float4 va0 = *(const float4*)(ap);
        float4 va1 = *(const float4*)(ap + 4);
        float4 va2 = *(const float4*)(ap + 8);
        float4 va3 = *(const float4*)(ap + 12);
        float4 vb0 = *(const float4*)(bp);
        float4 vb1 = *(const float4*)(bp + 4);
        float4 vb2 = *(const float4*)(bp + 8);
        float4 vb3 = *(const float4*)(bp + 12);
        uint32_t h[4], l[4];
        split2(va0.x, va0.y, h[0], l[0]);
        split2(va0.z, va0.w, h[1], l[1]);
        split2(va1.x, va1.y, h[2], l[2]);
        split2(va1.z, va1.w, h[3], l[3]);
        *(uint4*)(smem + bufOff + aOffH) = make_uint4(h[0], h[1], h[2], h[3]);
        *(uint4*)(smem + bufOff + aOffL) = make_uint4(l[0], l[1], l[2], l[3]);
        split2(va2.x, va2.y, h[0], l[0]);
        split2(va2.z, va2.w, h[1], l[1]);
        split2(va3.x, va3.y, h[2], l[2]);
        split2(va3.z, va3.w, h[3], l[3]);
        *(uint4*)(smem + bufOff + aOffH + 16) = make_uint4(h[0], h[1], h[2], h[3]);
        *(uint4*)(smem + bufOff + aOffL + 16) = make_uint4(l[0], l[1], l[2], l[3]);
        split2(vb0.x, vb0.y, h[0], l[0]);
        split2(vb0.z, vb0.w, h[1], l[1]);
        split2(vb1.x, vb1.y, h[2], l[2]);
        split2(vb1.z, vb1.w, h[3], l[3]);
        *(uint4*)(smem + bufOff + bOffH) = make_uint4(h[0], h[1], h[2], h[3]);
        *(uint4*)(smem + bufOff + bOffL) = make_uint4(l[0], l[1], l[2], l[3]);
        split2(vb2.x, vb2.y, h[0], l[0]);
        split2(vb2.z, vb2.w, h[1], l[1]);
        split2(vb3.x, vb3.y, h[2], l[2]);
        split2(vb3.z, vb3.w, h[3], l[3]);
        *(uint4*)(smem + bufOff + bOffH + 16) = make_uint4(h[0], h[1], h[2], h[3]);
        *(uint4*)(smem + bufOff + bOffL + 16) = make_uint4(l[0], l[1], l[2], l[3]);
    };

    auto mmaStep = [&](int kk, uint32_t bufOff) {
        uint32_t ah[2][4], al[2][4], bf[4][4];
#pragma unroll
        for (int t = 0; t < 2; ++t) {
            ldsm4(ah[t], sb + bufOff + aFH[t] + kk * 32);
            ldsm4(al[t], sb + bufOff + aFL[t] + kk * 32);
        }
#pragma unroll
        for (int p = 0; p < 4; ++p) ldsm4t(bf[p], sb + bufOff + bFH[p] + kk * 16 * B_STR);
#pragma unroll
        for (int t = 0; t < 2; ++t)
#pragma unroll
            for (int nt = 0; nt < 8; ++nt)
                mma16816(acc[t][nt], ah[t], &bf[nt >> 1][(nt & 1) * 2]);
#pragma unroll
        for (int t = 0; t < 2; ++t)
#pragma unroll
            for (int nt = 0; nt < 8; ++nt)
                mma16816(acc[t][nt], al[t], &bf[nt >> 1][(nt & 1) * 2]);
#pragma unroll
        for (int p = 0; p < 4; ++p) ldsm4t(bf[p], sb + bufOff + bFL[p] + kk * 16 * B_STR);
#pragma unroll
        for (int t = 0; t < 2; ++t)
#pragma unroll
            for (int nt = 0; nt < 8; ++nt)
                mma16816(acc[t][nt], ah[t], &bf[nt >> 1][(nt & 1) * 2]);
    };

    loadStore(0, 0);
    __syncthreads();

    int KT = K / 32;
    for (int kc = 0; kc < KT; ++kc) {
        uint32_t curOff = (kc & 1) ? (uint32_t)SM_TOT : 0u;
        uint32_t nxtOff = SM_TOT - curOff;
        bool more = (kc + 1 < KT);
        mmaStep(0, curOff);
        if (more) loadStore(kc + 1, nxtOff);   // LDG stall covered by co-resident warps' MMAs
        mmaStep(1, curOff);
        __syncthreads();
    }

    // ---- epilogue ----
    const float* sp = scaleBase ? scaleBase + (long)(scaleMod ? (z % scaleMod) : z) * DD : nullptr;
#pragma unroll
    for (int t = 0; t < 2; ++t) {
        int row = m0 + wm * 32 + t * 16 + (lane >> 2);
        float s0 = 1.0f, s1 = 1.0f;
        if (sp) { s0 = 1.0f / sp[row]; s1 = 1.0f / sp[row + 8]; }
#pragma unroll
        for (int nt = 0; nt < 8; ++nt) {
            int col = n0 + wn * 64 + nt * 8 + (lane & 3) * 2;
            float bx = 0.0f, by = 0.0f;
            if (bias) { float2 bb = *(const float2*)(bias + col); bx = bb.x; by = bb.y; }
            float2 v0 = make_float2(acc[t][nt][0] * s0 + bx, acc[t][nt][1] * s0 + by);
            float2 v1 = make_float2(acc[t][nt][2] * s1 + bx, acc[t][nt][3] * s1 + by);
            *(float2*)&C[(long)row * ldc + col] = v0;
            *(float2*)&C[(long)(row + 8) * ldc + col] = v1;
        }
    }
}

// ---------------- launch -----------------------------------------------------
extern "C" void kernel_launch(void* const* d_in, const int* in_sizes, int n_in,
                              void* d_out, int out_size)
{
    const float* value = (const float*)d_in[0];
    const float* emb   = (const float*)d_in[1];
    const float* Wqk   = (const float*)d_in[2];
    const float* bqk   = (const float*)d_in[3];
    const float* Wv    = (const float*)d_in[4];
    const float* bv    = (const float*)d_in[5];
    float* out = (float*)d_out;

    void *pq, *pET, *pcs, *pkv, *pP;
    cudaGetSymbolAddress(&pq, g_q);
    cudaGetSymbolAddress(&pET, g_ET);
    cudaGetSymbolAddress(&pcs, g_cs);
    cudaGetSymbolAddress(&pkv, g_kv);
    cudaGetSymbolAddress(&pP, g_P);

    static int smemSet = 0;
    if (!smemSet) {
        cudaFuncSetAttribute(gemm_mma, cudaFuncAttributeMaxDynamicSharedMemorySize, SM_DBL);
        smemSet = 1;
    }

    qk_kernel<<<NN * SS / SROWS, 256>>>(emb, Wqk, bqk);
    colsum_kernel<<<NN * DD / 8, 256>>>();

    // GEMM1: kv[d,e] = (sum_s ET[d,s] * value[s,e]) / colsum[d]
    gemm_mma<<<dim3(2, 2, BB * NN), 256, SM_DBL>>>(
        (const float*)pET, value, (float*)pkv,
        SS, SS, DD, DD,
        (long)DD * SS, NN,
        (long)SS * DD, 0,
        (long)DD * DD,
        (const float*)pcs, NN, nullptr);

    // GEMM2: P[d,e] = sum_f kv[d,f] * Wv[f,e]
    gemm_mma<<<dim3(2, 2, BB * NN), 256, SM_DBL>>>(
        (const float*)pkv, Wv, (float*)pP,
        DD, DD, DD, DD,
        (long)DD * DD, 0,
        0L, 0,
        (long)DD * DD,
        nullptr, 0, nullptr);

    // GEMM3: out[s,e] = sum_d q[s,d] * P[d,e] + bv[e]
    gemm_mma<<<dim3(2, 4, BB * NN), 256, SM_DBL>>>(
        (const float*)pq, (const float*)pP, out,
        DD, DD, DD, DD,
        (long)SS * DD, NN,
        (long)DD * DD, 0,
        (long)SS * DD,
        nullptr, 0, bv);
}

// round 8
// speedup vs baseline: 2.3939x; 1.1247x over previous
#include <cuda_runtime.h>
#include <cuda_fp16.h>
#include <cstdint>
#include <math.h>

#define BB 32
#define NN 12
#define SS 512
#define DD 256
#define AA 96

// ---------------- scratch (device globals) -----------------------------------
static __device__ float g_q[NN * SS * DD];                  // q softmax [n][s][d]
static __device__ float g_ET[NN * DD * SS];                 // exp(qk)^T [n][d][s]
static __device__ float g_cs[NN * DD];                      // colsum over s
static __device__ float g_kv[(size_t)BB * NN * DD * DD];    // kv [bn][d][e]
static __device__ float g_P[(size_t)BB * NN * DD * DD];     // P  [bn][d][e]

// ---------------- helpers ----------------------------------------------------
__device__ __forceinline__ uint32_t smem_u32(const void* p) {
    uint32_t a;
    asm("{ .reg .u64 t; cvta.to.shared.u64 t, %1; cvt.u32.u64 %0, t; }" : "=r"(a) : "l"(p));
    return a;
}
__device__ __forceinline__ void ldsm4(uint32_t* r, uint32_t a) {
    asm volatile("ldmatrix.sync.aligned.m8n8.x4.shared.b16 {%0,%1,%2,%3}, [%4];"
                 : "=r"(r[0]), "=r"(r[1]), "=r"(r[2]), "=r"(r[3]) : "r"(a));
}
__device__ __forceinline__ void ldsm4t(uint32_t* r, uint32_t a) {
    asm volatile("ldmatrix.sync.aligned.m8n8.x4.trans.shared.b16 {%0,%1,%2,%3}, [%4];"
                 : "=r"(r[0]), "=r"(r[1]), "=r"(r[2]), "=r"(r[3]) : "r"(a));
}
__device__ __forceinline__ void mma16816(float* c, const uint32_t* a, const uint32_t* b) {
    asm volatile("mma.sync.aligned.m16n8k16.row.col.f32.f16.f16.f32 "
                 "{%0,%1,%2,%3}, {%4,%5,%6,%7}, {%8,%9}, {%0,%1,%2,%3};"
                 : "+f"(c[0]), "+f"(c[1]), "+f"(c[2]), "+f"(c[3])
                 : "r"(a[0]), "r"(a[1]), "r"(a[2]), "r"(a[3]), "r"(b[0]), "r"(b[1]));
}
// fp16 split: a = hi + lo (hi = fp16(a), lo = fp16(a - hi)); packed pairs
__device__ __forceinline__ void split2h(float x, float y, uint32_t& h, uint32_t& l) {
    __half hx = __float2half_rn(x), hy = __float2half_rn(y);
    __half lx = __float2half_rn(x - __half2float(hx));
    __half ly = __float2half_rn(y - __half2float(hy));
    __half2 hv; hv.x = hx; hv.y = hy;
    __half2 lv; lv.x = lx; lv.y = ly;
    h = *(uint32_t*)&hv;
    l = *(uint32_t*)&lv;
}
__device__ __forceinline__ uint32_t pack2h(float x, float y) {
    __half2 hv; hv.x = __float2half_rn(x); hv.y = __float2half_rn(y);
    return *(uint32_t*)&hv;
}

// ---------------- qk kernel: 32 s-rows/block, SMEM transpose for coalesced ET -
#define QROWS 32
__global__ __launch_bounds__(256)
void qk_kernel(const float* __restrict__ emb,
               const float* __restrict__ Wqk,
               const float* __restrict__ bqk)
{
    int n = blockIdx.x / (SS / QROWS);
    int s0 = (blockIdx.x % (SS / QROWS)) * QROWS;

    __shared__ float se[QROWS][AA];      // emb tile  (12.3 KB)
    __shared__ float es[QROWS][257];     // exp tile, stride 257 (32.9 KB)

    int tid = threadIdx.x;

    // load emb tile (coalesced)
    for (int i = tid; i < QROWS * AA; i += 256)
        se[i / AA][i % AA] = emb[((size_t)(n * SS + s0)) * AA + i];
    __syncthreads();

    int sy = tid >> 5;          // warp -> 4 s-rows sy*4..+3
    int dx = tid & 31;          // lane -> d = j*32+dx

    float acc[4][8];
#pragma unroll
    for (int j = 0; j < 8; ++j) {
        float b = bqk[j * 32 + dx];
#pragma unroll
        for (int i = 0; i < 4; ++i) acc[i][j] = b;
    }
#pragma unroll 2
    for (int a = 0; a < AA; ++a) {
        float w[8];
#pragma unroll
        for (int j = 0; j < 8; ++j) w[j] = Wqk[a * DD + j * 32 + dx];
        float sv0 = se[sy * 4 + 0][a], sv1 = se[sy * 4 + 1][a];
        float sv2 = se[sy * 4 + 2][a], sv3 = se[sy * 4 + 3][a];
#pragma unroll
        for (int j = 0; j < 8; ++j) {
            acc[0][j] = fmaf(sv0, w[j], acc[0][j]);
            acc[1][j] = fmaf(sv1, w[j], acc[1][j]);
            acc[2][j] = fmaf(sv2, w[j], acc[2][j]);
            acc[3][j] = fmaf(sv3, w[j], acc[3][j]);
        }
    }

    // exp + warp rowsums (no block barriers)
#pragma unroll
    for (int i = 0; i < 4; ++i) {
        float loc = 0.0f;
#pragma unroll
        for (int j = 0; j < 8; ++j) { acc[i][j] = expf(acc[i][j]); loc += acc[i][j]; }
#pragma unroll
        for (int off = 16; off > 0; off >>= 1) loc += __shfl_xor_sync(0xffffffff, loc, off);
        float inv = 1.0f / loc;
        int s = s0 + sy * 4 + i;
#pragma unroll
        for (int j = 0; j < 8; ++j) {
            g_q[((size_t)(n * SS + s)) * DD + j * 32 + dx] = acc[i][j] * inv;
            es[sy * 4 + i][j * 32 + dx] = acc[i][j];
        }
    }
    __syncthreads();

    // transposed coalesced write: thread covers 32 s of 8 d-rows (128B each)
    int dq = tid >> 3;           // 0..31 (d within pass)
    int sq = (tid & 7) * 4;      // 4-s group
#pragma unroll
    for (int pass = 0; pass < 8; ++pass) {
        int d = pass * 32 + dq;
        float4 v = make_float4(es[sq + 0][d], es[sq + 1][d], es[sq + 2][d], es[sq + 3][d]);
        *(float4*)&g_ET[((size_t)n * DD + d) * SS + s0 + sq] = v;
    }
}

__global__ void colsum_kernel()
{
    int r = blockIdx.x * 8 + (threadIdx.x >> 5);
    int l = threadIdx.x & 31;
    const float4* p = (const float4*)(g_ET + (size_t)r * SS);
    float4 a = p[l], b = p[l + 32], c = p[l + 64], d4 = p[l + 96];
    float s = a.x + a.y + a.z + a.w + b.x + b.y + b.z + b.w
            + c.x + c.y + c.z + c.w + d4.x + d4.y + d4.z + d4.w;
#pragma unroll
    for (int off = 16; off > 0; off >>= 1) s += __shfl_xor_sync(0xffffffff, s, off);
    if (l == 0) g_cs[r] = s;
}

// ---------------- warp-MMA fp16 2-term-split batched GEMM --------------------
// C[m,n] = sum_k A[m,k] * B[k,n]   (A row-major, B row-major; B trans via ldmatrix)
// a = ah + al (fp16 each); C ~= ah*bh + al*bh; fp32 accumulate.
// Dropped term a*bl: |bl| <= 2^-11 |b|  -> rel_err ~2e-4 (within 1e-3).
#define A_STR 80
#define B_STR 272
#define SM_AH 0
#define SM_AL 10240
#define SM_BH 20480
#define SM_TOT 29184
#define SM_DBL (2 * SM_TOT)

__global__ __launch_bounds__(256, 2)
void gemm_mma(const float* __restrict__ Ag, const float* __restrict__ Bg,
              float* __restrict__ Cg, int K, int lda, int ldb, int ldc,
              long aStride, int aMod, long bStride, int bMod, long cStride,
              const float* __restrict__ scaleBase, int scaleMod,
              const float* __restrict__ bias)
{
    extern __shared__ __align__(16) char smem[];

    int z = blockIdx.z;
    const float* A = Ag + (long)(aMod ? (z % aMod) : z) * aStride;
    const float* B = Bg + (long)(bMod ? (z % bMod) : z) * bStride;
    float* C = Cg + (long)z * cStride;
    int m0 = blockIdx.y * 128, n0 = blockIdx.x * 128;

    int tid = threadIdx.x, lane = tid & 31, wid = tid >> 5;
    int wm = wid >> 1, wn = wid & 1;       // warp tile: 32(M) x 64(N)

    int arow = tid >> 1, akb = (tid & 1) * 16;
    int brow = tid >> 3, bnb = (tid & 7) * 16;
    const float* aPtr = A + (long)(m0 + arow) * lda + akb;
    const float* bPtr = B + (long)brow * ldb + n0 + bnb;

    uint32_t sb = smem_u32(smem);
    uint32_t aOffH = SM_AH + arow * A_STR + akb * 2;
    uint32_t aOffL = SM_AL + arow * A_STR + akb * 2;
    uint32_t bOffH = SM_BH + brow * B_STR + bnb * 2;

    uint32_t aFH[2], aFL[2], bFH[4];
#pragma unroll
    for (int t = 0; t < 2; ++t) {
        uint32_t off = (uint32_t)((wm * 32 + t * 16 + (lane & 15)) * A_STR + (lane >> 4) * 16);
        aFH[t] = SM_AH + off;
        aFL[t] = SM_AL + off;
    }
#pragma unroll
    for (int p = 0; p < 4; ++p) {
        uint32_t off = (uint32_t)((lane & 15) * B_STR + (wn * 64 + p * 16 + (lane >> 4) * 8) * 2);
        bFH[p] = SM_BH + off;
    }

    float acc[2][8][4];
#pragma unroll
    for (int t = 0; t < 2; ++t)
#pragma unroll
        for (int nt = 0; nt < 8; ++nt)
#pragma unroll
            for (int j = 0; j < 4; ++j) acc[t][nt][j] = 0.0f;

    auto loadStore = [&](int kc, uint32_t bufOff) {
        const float* ap = aPtr + kc * 32;
        const float* bp = bPtr + (long)kc * 32 * ldb;
        float4 va0 = *(const float4*)(ap);
        float4 va1 = *(const float4*)(ap + 4);
        float4 va2 = *(const float4*)(ap + 8);
        float4 va3 = *(const float4*)(ap + 12);
        float4 vb0 = *(const float4*)(bp);
        float4 vb1 = *(const float4*)(bp + 4);
        float4 vb2 = *(const float4*)(bp + 8);
        float4 vb3 = *(const float4*)(bp + 12);
        uint32_t h[4], l[4];
        split2h(va0.x, va0.y, h[0], l[0]);
        split2h(va0.z, va0.w, h[1], l[1]);
        split2h(va1.x, va1.y, h[2], l[2]);
        split2h(va1.z, va1.w, h[3], l[3]);
        *(uint4*)(smem + bufOff + aOffH) = make_uint4(h[0], h[1], h[2], h[3]);
        *(uint4*)(smem + bufOff + aOffL) = make_uint4(l[0], l[1], l[2], l[3]);
        split2h(va2.x, va2.y, h[0], l[0]);
        split2h(va2.z, va2.w, h[1], l[1]);
        split2h(va3.x, va3.y, h[2], l[2]);
        split2h(va3.z, va3.w, h[3], l[3]);
        *(uint4*)(smem + bufOff + aOffH + 16) = make_uint4(h[0], h[1], h[2], h[3]);
        *(uint4*)(smem + bufOff + aOffL + 16) = make_uint4(l[0], l[1], l[2], l[3]);
        // B: hi only
        *(uint4*)(smem + bufOff + bOffH) = make_uint4(
            pack2h(vb0.x, vb0.y), pack2h(vb0.z, vb0.w),
            pack2h(vb1.x, vb1.y), pack2h(vb1.z, vb1.w));
        *(uint4*)(smem + bufOff + bOffH + 16) = make_uint4(
            pack2h(vb2.x, vb2.y), pack2h(vb2.z, vb2.w),
            pack2h(vb3.x, vb3.y), pack2h(vb3.z, vb3.w));
    };

    auto mmaStep = [&](int kk, uint32_t bufOff) {
        uint32_t ah[2][4], al[2][4], bf[4][4];
#pragma unroll
        for (int t = 0; t < 2; ++t) {
            ldsm4(ah[t], sb + bufOff + aFH[t] + kk * 32);
            ldsm4(al[t], sb + bufOff + aFL[t] + kk * 32);
        }
#pragma unroll
        for (int p = 0; p < 4; ++p) ldsm4t(bf[p], sb + bufOff + bFH[p] + kk * 16 * B_STR);
#pragma unroll
        for (int t = 0; t < 2; ++t)
#pragma unroll
            for (int nt = 0; nt < 8; ++nt)
                mma16816(acc[t][nt], ah[t], &bf[nt >> 1][(nt & 1) * 2]);
#pragma unroll
        for (int t = 0; t < 2; ++t)
#pragma unroll
            for (int nt = 0; nt < 8; ++nt)
                mma16816(acc[t][nt], al[t], &bf[nt >> 1][(nt & 1) * 2]);
    };

    loadStore(0, 0);
    __syncthreads();

    int KT = K / 32;
    for (int kc = 0; kc < KT; ++kc) {
        uint32_t curOff = (kc & 1) ? (uint32_t)SM_TOT : 0u;
        uint32_t nxtOff = SM_TOT - curOff;
        bool more = (kc + 1 < KT);
        mmaStep(0, curOff);
        if (more) loadStore(kc + 1, nxtOff);
        mmaStep(1, curOff);
        __syncthreads();
    }

    // ---- epilogue ----
    const float* sp = scaleBase ? scaleBase + (long)(scaleMod ? (z % scaleMod) : z) * DD : nullptr;
#pragma unroll
    for (int t = 0; t < 2; ++t) {
        int row = m0 + wm * 32 + t * 16 + (lane >> 2);
        float s0 = 1.0f, s1 = 1.0f;
        if (sp) { s0 = 1.0f / sp[row]; s1 = 1.0f / sp[row + 8]; }
#pragma unroll
        for (int nt = 0; nt < 8; ++nt) {
            int col = n0 + wn * 64 + nt * 8 + (lane & 3) * 2;
            float bx = 0.0f, by = 0.0f;
            if (bias) { float2 bb = *(const float2*)(bias + col); bx = bb.x; by = bb.y; }
            float2 v0 = make_float2(acc[t][nt][0] * s0 + bx, acc[t][nt][1] * s0 + by);
            float2 v1 = make_float2(acc[t][nt][2] * s1 + bx, acc[t][nt][3] * s1 + by);
            *(float2*)&C[(long)row * ldc + col] = v0;
            *(float2*)&C[(long)(row + 8) * ldc + col] = v1;
        }
    }
}

// ---------------- launch -----------------------------------------------------
extern "C" void kernel_launch(void* const* d_in, const int* in_sizes, int n_in,
                              void* d_out, int out_size)
{
    const float* value = (const float*)d_in[0];
    const float* emb   = (const float*)d_in[1];
    const float* Wqk   = (const float*)d_in[2];
    const float* bqk   = (const float*)d_in[3];
    const float* Wv    = (const float*)d_in[4];
    const float* bv    = (const float*)d_in[5];
    float* out = (float*)d_out;

    void *pq, *pET, *pcs, *pkv, *pP;
    cudaGetSymbolAddress(&pq, g_q);
    cudaGetSymbolAddress(&pET, g_ET);
    cudaGetSymbolAddress(&pcs, g_cs);
    cudaGetSymbolAddress(&pkv, g_kv);
    cudaGetSymbolAddress(&pP, g_P);

    static int smemSet = 0;
    if (!smemSet) {
        cudaFuncSetAttribute(gemm_mma, cudaFuncAttributeMaxDynamicSharedMemorySize, SM_DBL);
        smemSet = 1;
    }

    qk_kernel<<<NN * (SS / QROWS), 256>>>(emb, Wqk, bqk);
    colsum_kernel<<<NN * DD / 8, 256>>>();

    // GEMM1: kv[d,e] = (sum_s ET[d,s] * value[s,e]) / colsum[d]
    gemm_mma<<<dim3(2, 2, BB * NN), 256, SM_DBL>>>(
        (const float*)pET, value, (float*)pkv,
        SS, SS, DD, DD,
        (long)DD * SS, NN,
        (long)SS * DD, 0,
        (long)DD * DD,
        (const float*)pcs, NN, nullptr);

    // GEMM2: P[d,e] = sum_f kv[d,f] * Wv[f,e]
    gemm_mma<<<dim3(2, 2, BB * NN), 256, SM_DBL>>>(
        (const float*)pkv, Wv, (float*)pP,
        DD, DD, DD, DD,
        (long)DD * DD, 0,
        0L, 0,
        (long)DD * DD,
        nullptr, 0, nullptr);

    // GEMM3: out[s,e] = sum_d q[s,d] * P[d,e] + bv[e]
    gemm_mma<<<dim3(2, 4, BB * NN), 256, SM_DBL>>>(
        (const float*)pq, (const float*)pP, out,
        DD, DD, DD, DD,
        (long)SS * DD, NN,
        (long)DD * DD, 0,
        (long)SS * DD,
        nullptr, 0, bv);
}

// round 10
// speedup vs baseline: 2.6053x; 1.0883x over previous
#include <cuda_runtime.h>
#include <cuda_fp16.h>
#include <cstdint>
#include <math.h>

#define BB 32
#define NN 12
#define SS 512
#define DD 256
#define AA 96

// ---------------- scratch (device globals, fp16 planes) ----------------------
static __device__ __align__(16) __half g_qh[NN * SS * DD];
static __device__ __align__(16) __half g_ql[NN * SS * DD];
static __device__ __align__(16) __half g_ETh[NN * DD * SS];
static __device__ __align__(16) __half g_ETl[NN * DD * SS];
static __device__ float g_cs[NN * DD];
static __device__ __align__(16) __half g_kvh[(size_t)BB * NN * DD * DD];
static __device__ __align__(16) __half g_kvl[(size_t)BB * NN * DD * DD];
static __device__ __align__(16) __half g_Ph[(size_t)BB * NN * DD * DD];

// ---------------- helpers ----------------------------------------------------
__device__ __forceinline__ uint32_t smem_u32(const void* p) {
    uint32_t a;
    asm("{ .reg .u64 t; cvta.to.shared.u64 t, %1; cvt.u32.u64 %0, t; }" : "=r"(a) : "l"(p));
    return a;
}
__device__ __forceinline__ void ldsm4(uint32_t* r, uint32_t a) {
    asm volatile("ldmatrix.sync.aligned.m8n8.x4.shared.b16 {%0,%1,%2,%3}, [%4];"
                 : "=r"(r[0]), "=r"(r[1]), "=r"(r[2]), "=r"(r[3]) : "r"(a));
}
__device__ __forceinline__ void ldsm4t(uint32_t* r, uint32_t a) {
    asm volatile("ldmatrix.sync.aligned.m8n8.x4.trans.shared.b16 {%0,%1,%2,%3}, [%4];"
                 : "=r"(r[0]), "=r"(r[1]), "=r"(r[2]), "=r"(r[3]) : "r"(a));
}
__device__ __forceinline__ void mma16816(float* c, const uint32_t* a, const uint32_t* b) {
    asm volatile("mma.sync.aligned.m16n8k16.row.col.f32.f16.f16.f32 "
                 "{%0,%1,%2,%3}, {%4,%5,%6,%7}, {%8,%9}, {%0,%1,%2,%3};"
                 : "+f"(c[0]), "+f"(c[1]), "+f"(c[2]), "+f"(c[3])
                 : "r"(a[0]), "r"(a[1]), "r"(a[2]), "r"(a[3]), "r"(b[0]), "r"(b[1]));
}
__device__ __forceinline__ void hsplit(float x, __half& h, __half& l) {
    h = __float2half_rn(x);
    l = __float2half_rn(x - __half2float(h));
}
__device__ __forceinline__ uint32_t pack2h(float x, float y) {
    __half2 hv; hv.x = __float2half_rn(x); hv.y = __float2half_rn(y);
    return *(uint32_t*)&hv;
}
#define CP16(dst, src) \
    asm volatile("cp.async.cg.shared.global [%0], [%1], 16;" :: "r"(dst), "l"(src))
#define CP_COMMIT() asm volatile("cp.async.commit_group;" ::: "memory")
#define CP_WAIT0()  asm volatile("cp.async.wait_group 0;" ::: "memory")

// ---------------- qk kernel: writes q hi/lo planes + ET hi/lo planes ----------
#define QROWS 32
__global__ __launch_bounds__(256)
void qk_kernel(const float* __restrict__ emb,
               const float* __restrict__ Wqk,
               const float* __restrict__ bqk)
{
    int n = blockIdx.x / (SS / QROWS);
    int s0 = (blockIdx.x % (SS / QROWS)) * QROWS;

    __shared__ float se[QROWS][AA];
    __shared__ float es[QROWS][257];

    int tid = threadIdx.x;
    for (int i = tid; i < QROWS * AA; i += 256)
        se[i / AA][i % AA] = emb[((size_t)(n * SS + s0)) * AA + i];
    __syncthreads();

    int sy = tid >> 5;
    int dx = tid & 31;

    float acc[4][8];
#pragma unroll
    for (int j = 0; j < 8; ++j) {
        float b = bqk[j * 32 + dx];
#pragma unroll
        for (int i = 0; i < 4; ++i) acc[i][j] = b;
    }
#pragma unroll 2
    for (int a = 0; a < AA; ++a) {
        float w[8];
#pragma unroll
        for (int j = 0; j < 8; ++j) w[j] = Wqk[a * DD + j * 32 + dx];
        float sv0 = se[sy * 4 + 0][a], sv1 = se[sy * 4 + 1][a];
        float sv2 = se[sy * 4 + 2][a], sv3 = se[sy * 4 + 3][a];
#pragma unroll
        for (int j = 0; j < 8; ++j) {
            acc[0][j] = fmaf(sv0, w[j], acc[0][j]);
            acc[1][j] = fmaf(sv1, w[j], acc[1][j]);
            acc[2][j] = fmaf(sv2, w[j], acc[2][j]);
            acc[3][j] = fmaf(sv3, w[j], acc[3][j]);
        }
    }

#pragma unroll
    for (int i = 0; i < 4; ++i) {
        float loc = 0.0f;
#pragma unroll
        for (int j = 0; j < 8; ++j) { acc[i][j] = expf(acc[i][j]); loc += acc[i][j]; }
#pragma unroll
        for (int off = 16; off > 0; off >>= 1) loc += __shfl_xor_sync(0xffffffff, loc, off);
        float inv = 1.0f / loc;
        int s = s0 + sy * 4 + i;
#pragma unroll
        for (int j = 0; j < 8; ++j) {
            size_t idx = ((size_t)(n * SS + s)) * DD + j * 32 + dx;
            __half h, l;
            hsplit(acc[i][j] * inv, h, l);
            g_qh[idx] = h;
            g_ql[idx] = l;
            es[sy * 4 + i][j * 32 + dx] = acc[i][j];
        }
    }
    __syncthreads();

    // transposed coalesced writes of ET hi/lo planes (8B per plane per pass)
    int dq = tid >> 3;
    int sq = (tid & 7) * 4;
#pragma unroll
    for (int pass = 0; pass < 8; ++pass) {
        int d = pass * 32 + dq;
        float v0 = es[sq + 0][d], v1 = es[sq + 1][d], v2 = es[sq + 2][d], v3 = es[sq + 3][d];
        __half h0, l0, h1, l1, h2, l2, h3, l3;
        hsplit(v0, h0, l0); hsplit(v1, h1, l1); hsplit(v2, h2, l2); hsplit(v3, h3, l3);
        size_t base = ((size_t)n * DD + d) * SS + s0 + sq;
        __half2 a = __halves2half2(h0, h1), b = __halves2half2(h2, h3);
        uint2 uh; uh.x = *(uint32_t*)&a; uh.y = *(uint32_t*)&b;
        *(uint2*)&g_ETh[base] = uh;
        __half2 c = __halves2half2(l0, l1), dl = __halves2half2(l2, l3);
        uint2 ul; ul.x = *(uint32_t*)&c; ul.y = *(uint32_t*)&dl;
        *(uint2*)&g_ETl[base] = ul;
    }
}

// colsum from hi+lo planes
__global__ void colsum_kernel()
{
    int r = blockIdx.x * 8 + (threadIdx.x >> 5);
    int l = threadIdx.x & 31;
    const uint4* ph = (const uint4*)(g_ETh + (size_t)r * SS);
    const uint4* pl = (const uint4*)(g_ETl + (size_t)r * SS);
    float s = 0.0f;
#pragma unroll
    for (int c = 0; c < 2; ++c) {
        uint4 a = ph[l + c * 32];
        uint4 b = pl[l + c * 32];
        const __half2* pa = (const __half2*)&a;
        const __half2* pb = (const __half2*)&b;
#pragma unroll
        for (int j = 0; j < 4; ++j) {
            float2 fa = __half22float2(pa[j]);
            float2 fb = __half22float2(pb[j]);
            s += fa.x + fa.y + fb.x + fb.y;
        }
    }
#pragma unroll
    for (int off = 16; off > 0; off >>= 1) s += __shfl_xor_sync(0xffffffff, s, off);
    if (l == 0) g_cs[r] = s;
}

// ---------------- warp-MMA fp16 2-term-split batched GEMM --------------------
// A given as pre-split hi/lo fp16 planes (cp.async). B either fp32 (convert
// in-kernel, hi only) or pre-split fp16 hi plane (cp.async).
// OMODE: 0 = fp32 out + bias; 1 = half hi/lo planes + row scale; 2 = half hi.
#define A_STR 80
#define B_STR 272
#define SM_AH 0
#define SM_AL 10240
#define SM_BH 20480
#define SM_TOT 29184
#define SM_DBL (2 * SM_TOT)

template<bool BF32, int OMODE>
__global__ __launch_bounds__(256, 2)
void gemm_mma(const __half* __restrict__ Ahg, const __half* __restrict__ Alg,
              const void* __restrict__ Bg,
              void* __restrict__ Cg, void* __restrict__ C2g,
              int K, int ldb, int ldc,
              long aStride, int aMod, long bStride, int bMod, long cStride,
              const float* __restrict__ scaleBase, int scaleMod,
              const float* __restrict__ bias)
{
    extern __shared__ __align__(16) char smem[];

    int z = blockIdx.z;
    const __half* Ah = Ahg + (long)(aMod ? (z % aMod) : z) * aStride;
    const __half* Al = Alg + (long)(aMod ? (z % aMod) : z) * aStride;
    int m0 = blockIdx.y * 128, n0 = blockIdx.x * 128;

    int tid = threadIdx.x, lane = tid & 31, wid = tid >> 5;
    int wm = wid >> 1, wn = wid & 1;

    uint32_t sb = smem_u32(smem);

    // A cp.async map: row = tid>>1, two 16B units u,u+1 with u=(tid&1)*2
    int arow = tid >> 1;
    int au = (tid & 1) * 2;
    const __half* aSrcH = Ah + (size_t)(m0 + arow) * K + au * 8;
    const __half* aSrcL = Al + (size_t)(m0 + arow) * K + au * 8;
    uint32_t aDstH = sb + SM_AH + arow * A_STR + au * 16;
    uint32_t aDstL = sb + SM_AL + arow * A_STR + au * 16;

    // B maps
    int brow, bu = 0, bnb = 0;
    const __half* bSrcH = nullptr;
    const float* bPtr = nullptr;
    uint32_t bDst = 0, bOffH = 0;
    if (BF32) {
        brow = tid >> 3; bnb = (tid & 7) * 16;
        bPtr = (const float*)Bg + (long)(bMod ? (z % bMod) : z) * bStride
             + (long)brow * ldb + n0 + bnb;
        bOffH = SM_BH + brow * B_STR + bnb * 2;
    } else {
        brow = tid >> 3; bu = (tid & 7) * 2;
        bSrcH = (const __half*)Bg + (long)(bMod ? (z % bMod) : z) * bStride
              + (size_t)brow * ldb + n0 + bu * 8;
        bDst = sb + SM_BH + brow * B_STR + bu * 16;
    }

    uint32_t aFH[2], aFL[2], bFH[4];
#pragma unroll
    for (int t = 0; t < 2; ++t) {
        uint32_t off = (uint32_t)((wm * 32 + t * 16 + (lane & 15)) * A_STR + (lane >> 4) * 16);
        aFH[t] = SM_AH + off;
        aFL[t] = SM_AL + off;
    }
#pragma unroll
    for (int p = 0; p < 4; ++p) {
        uint32_t off = (uint32_t)((lane & 15) * B_STR + (wn * 64 + p * 16 + (lane >> 4) * 8) * 2);
        bFH[p] = SM_BH + off;
    }

    float acc[2][8][4];
#pragma unroll
    for (int t = 0; t < 2; ++t)
#pragma unroll
        for (int nt = 0; nt < 8; ++nt)
#pragma unroll
            for (int j = 0; j < 4; ++j) acc[t][nt][j] = 0.0f;

    auto cpAsyncLoad = [&](int kc, uint32_t bufOff) {
        const __half* sh = aSrcH + kc * 32;
        const __half* sl = aSrcL + kc * 32;
        CP16(aDstH + bufOff, sh);
        CP16(aDstH + bufOff + 16, sh + 8);
        CP16(aDstL + bufOff, sl);
        CP16(aDstL + bufOff + 16, sl + 8);
        if (!BF32) {
            const __half* sbp = bSrcH + (size_t)kc * 32 * ldb;
            CP16(bDst + bufOff, sbp);
            CP16(bDst + bufOff + 16, sbp + 8);
        }
    };
    auto bConvStore = [&](int kc, uint32_t bufOff) {
        const float* bp = bPtr + (size_t)kc * 32 * ldb;
        float4 vb0 = *(const float4*)(bp);
        float4 vb1 = *(const float4*)(bp + 4);
        float4 vb2 = *(const float4*)(bp + 8);
        float4 vb3 = *(const float4*)(bp + 12);
        *(uint4*)(smem + bufOff + bOffH) = make_uint4(
            pack2h(vb0.x, vb0.y), pack2h(vb0.z, vb0.w),
            pack2h(vb1.x, vb1.y), pack2h(vb1.z, vb1.w));
        *(uint4*)(smem + bufOff + bOffH + 16) = make_uint4(
            pack2h(vb2.x, vb2.y), pack2h(vb2.z, vb2.w),
            pack2h(vb3.x, vb3.y), pack2h(vb3.z, vb3.w));
    };
    auto mmaStep = [&](int kk, uint32_t bufOff) {
        uint32_t ah[2][4], al[2][4], bf[4][4];
#pragma unroll
        for (int t = 0; t < 2; ++t) {
            ldsm4(ah[t], sb + bufOff + aFH[t] + kk * 32);
            ldsm4(al[t], sb + bufOff + aFL[t] + kk * 32);
        }
#pragma unroll
        for (int p = 0; p < 4; ++p) ldsm4t(bf[p], sb + bufOff + bFH[p] + kk * 16 * B_STR);
#pragma unroll
        for (int t = 0; t < 2; ++t)
#pragma unroll
            for (int nt = 0; nt < 8; ++nt)
                mma16816(acc[t][nt], ah[t], &bf[nt >> 1][(nt & 1) * 2]);
#pragma unroll
        for (int t = 0; t < 2; ++t)
#pragma unroll
            for (int nt = 0; nt < 8; ++nt)
                mma16816(acc[t][nt], al[t], &bf[nt >> 1][(nt & 1) * 2]);
    };

    // prologue
    cpAsyncLoad(0, 0);
    CP_COMMIT();
    if (BF32) bConvStore(0, 0);
    CP_WAIT0();
    __syncthreads();

    int KT = K / 32;
    for (int kc = 0; kc < KT; ++kc) {
        uint32_t curOff = (kc & 1) ? (uint32_t)SM_TOT : 0u;
        uint32_t nxtOff = SM_TOT - curOff;
        bool more = (kc + 1 < KT);
        if (more) { cpAsyncLoad(kc + 1, nxtOff); CP_COMMIT(); }
        mmaStep(0, curOff);
        if (more && BF32) bConvStore(kc + 1, nxtOff);
        mmaStep(1, curOff);
        CP_WAIT0();
        __syncthreads();
    }

    // ---- epilogue ----
    const float* sp = (OMODE == 1)
        ? scaleBase + (long)(scaleMod ? (z % scaleMod) : z) * DD : nullptr;
#pragma unroll
    for (int t = 0; t < 2; ++t) {
        int row = m0 + wm * 32 + t * 16 + (lane >> 2);
        float s0 = 1.0f, s1 = 1.0f;
        if (OMODE == 1) { s0 = 1.0f / sp[row]; s1 = 1.0f / sp[row + 8]; }
#pragma unroll
        for (int nt = 0; nt < 8; ++nt) {
            int col = n0 + wn * 64 + nt * 8 + (lane & 3) * 2;
            float v0 = acc[t][nt][0] * s0, v1 = acc[t][nt][1] * s0;
            float v2 = acc[t][nt][2] * s1, v3 = acc[t][nt][3] * s1;
            if (OMODE == 0) {
                float* C = (float*)Cg + (long)z * cStride;
                float2 bb = *(const float2*)(bias + col);
                *(float2*)&C[(long)row * ldc + col] = make_float2(v0 + bb.x, v1 + bb.y);
                *(float2*)&C[(long)(row + 8) * ldc + col] = make_float2(v2 + bb.x, v3 + bb.y);
            } else if (OMODE == 1) {
                __half* Ch = (__half*)Cg + (long)z * cStride;
                __half* Cl = (__half*)C2g + (long)z * cStride;
                __half h0, l0, h1, l1;
                hsplit(v0, h0, l0); hsplit(v1, h1, l1);
                *(__half2*)&Ch[(long)row * ldc + col] = __halves2half2(h0, h1);
                *(__half2*)&Cl[(long)row * ldc + col] = __halves2half2(l0, l1);
                hsplit(v2, h0, l0); hsplit(v3, h1, l1);
                *(__half2*)&Ch[(long)(row + 8) * ldc + col] = __halves2half2(h0, h1);
                *(__half2*)&Cl[(long)(row + 8) * ldc + col] = __halves2half2(l0, l1);
            } else {
                __half* Ch = (__half*)Cg + (long)z * cStride;
                *(__half2*)&Ch[(long)row * ldc + col] =
                    __halves2half2(__float2half_rn(v0), __float2half_rn(v1));
                *(__half2*)&Ch[(long)(row + 8) * ldc + col] =
                    __halves2half2(__float2half_rn(v2), __float2half_rn(v3));
            }
        }
    }
}

// ---------------- launch -----------------------------------------------------
extern "C" void kernel_launch(void* const* d_in, const int* in_sizes, int n_in,
                              void* d_out, int out_size)
{
    const float* value = (const float*)d_in[0];
    const float* emb   = (const float*)d_in[1];
    const float* Wqk   = (const float*)d_in[2];
    const float* bqk   = (const float*)d_in[3];
    const float* Wv    = (const float*)d_in[4];
    const float* bv    = (const float*)d_in[5];
    float* out = (float*)d_out;

    void *pqh, *pql, *pETh, *pETl, *pcs, *pkvh, *pkvl, *pPh;
    cudaGetSymbolAddress(&pqh, g_qh);
    cudaGetSymbolAddress(&pql, g_ql);
    cudaGetSymbolAddress(&pETh, g_ETh);
    cudaGetSymbolAddress(&pETl, g_ETl);
    cudaGetSymbolAddress(&pcs, g_cs);
    cudaGetSymbolAddress(&pkvh, g_kvh);
    cudaGetSymbolAddress(&pkvl, g_kvl);
    cudaGetSymbolAddress(&pPh, g_Ph);

    static int smemSet = 0;
    if (!smemSet) {
        cudaFuncSetAttribute(gemm_mma<true, 1>, cudaFuncAttributeMaxDynamicSharedMemorySize, SM_DBL);
        cudaFuncSetAttribute(gemm_mma<true, 2>, cudaFuncAttributeMaxDynamicSharedMemorySize, SM_DBL);
        cudaFuncSetAttribute(gemm_mma<false, 0>, cudaFuncAttributeMaxDynamicSharedMemorySize, SM_DBL);
        smemSet = 1;
    }

    qk_kernel<<<NN * (SS / QROWS), 256>>>(emb, Wqk, bqk);
    colsum_kernel<<<NN * DD / 8, 256>>>();

    // GEMM1: kv = (ET @ value) / colsum   -> kv hi/lo planes
    gemm_mma<true, 1><<<dim3(2, 2, BB * NN), 256, SM_DBL>>>(
        (const __half*)pETh, (const __half*)pETl, value,
        pkvh, pkvl,
        SS, DD, DD,
        (long)DD * SS, NN,
        (long)SS * DD, 0,
        (long)DD * DD,
        (const float*)pcs, NN, nullptr);

    // GEMM2: P = kv @ Wv   -> P hi plane only
    gemm_mma<true, 2><<<dim3(2, 2, BB * NN), 256, SM_DBL>>>(
        (const __half*)pkvh, (const __half*)pkvl, Wv,
        pPh, nullptr,
        DD, DD, DD,
        (long)DD * DD, 0,
        0L, 0,
        (long)DD * DD,
        nullptr, 0, nullptr);

    // GEMM3: out = q @ P + bv   (fp32 out)
    gemm_mma<false, 0><<<dim3(2, 4, BB * NN), 256, SM_DBL>>>(
        (const __half*)pqh, (const __half*)pql, pPh,
        out, nullptr,
        DD, DD, DD,
        (long)SS * DD, NN,
        (long)DD * DD, 0,
        (long)SS * DD,
        nullptr, 0, bv);
}

// round 12
// speedup vs baseline: 2.6411x; 1.0137x over previous
#include <cuda_runtime.h>
#include <cuda_fp16.h>
#include <cstdint>
#include <math.h>

#define BB 32
#define NN 12
#define SS 512
#define DD 256
#define AA 96

// ---------------- scratch (device globals, fp16 planes) ----------------------
static __device__ __align__(16) __half g_qh[NN * SS * DD];
static __device__ __align__(16) __half g_ql[NN * SS * DD];
static __device__ __align__(16) __half g_ETh[NN * DD * SS];
static __device__ __align__(16) __half g_ETl[NN * DD * SS];
static __device__ float g_cs[NN * DD];
static __device__ __align__(16) __half g_kvh[(size_t)BB * NN * DD * DD];
static __device__ __align__(16) __half g_kvl[(size_t)BB * NN * DD * DD];
static __device__ __align__(16) __half g_Ph[(size_t)BB * NN * DD * DD];

// ---------------- helpers ----------------------------------------------------
__device__ __forceinline__ uint32_t smem_u32(const void* p) {
    uint32_t a;
    asm("{ .reg .u64 t; cvta.to.shared.u64 t, %1; cvt.u32.u64 %0, t; }" : "=r"(a) : "l"(p));
    return a;
}
__device__ __forceinline__ void ldsm4(uint32_t* r, uint32_t a) {
    asm volatile("ldmatrix.sync.aligned.m8n8.x4.shared.b16 {%0,%1,%2,%3}, [%4];"
                 : "=r"(r[0]), "=r"(r[1]), "=r"(r[2]), "=r"(r[3]) : "r"(a));
}
__device__ __forceinline__ void ldsm4t(uint32_t* r, uint32_t a) {
    asm volatile("ldmatrix.sync.aligned.m8n8.x4.trans.shared.b16 {%0,%1,%2,%3}, [%4];"
                 : "=r"(r[0]), "=r"(r[1]), "=r"(r[2]), "=r"(r[3]) : "r"(a));
}
__device__ __forceinline__ void mma16816(float* c, const uint32_t* a, const uint32_t* b) {
    asm volatile("mma.sync.aligned.m16n8k16.row.col.f32.f16.f16.f32 "
                 "{%0,%1,%2,%3}, {%4,%5,%6,%7}, {%8,%9}, {%0,%1,%2,%3};"
                 : "+f"(c[0]), "+f"(c[1]), "+f"(c[2]), "+f"(c[3])
                 : "r"(a[0]), "r"(a[1]), "r"(a[2]), "r"(a[3]), "r"(b[0]), "r"(b[1]));
}
__device__ __forceinline__ void hsplit(float x, __half& h, __half& l) {
    h = __float2half_rn(x);
    l = __float2half_rn(x - __half2float(h));
}
__device__ __forceinline__ uint32_t pack2h(float x, float y) {
    __half2 hv; hv.x = __float2half_rn(x); hv.y = __float2half_rn(y);
    return *(uint32_t*)&hv;
}
#define CP16(dst, src) \
    asm volatile("cp.async.cg.shared.global [%0], [%1], 16;" :: "r"(dst), "l"(src))
#define CP_COMMIT() asm volatile("cp.async.commit_group;" ::: "memory")
#define CP_WAIT1()  asm volatile("cp.async.wait_group 1;" ::: "memory")
#define CP_WAIT0()  asm volatile("cp.async.wait_group 0;" ::: "memory")

// ---------------- qk kernel: writes q hi/lo planes + ET hi/lo planes ----------
#define QROWS 32
__global__ __launch_bounds__(256)
void qk_kernel(const float* __restrict__ emb,
               const float* __restrict__ Wqk,
               const float* __restrict__ bqk)
{
    int n = blockIdx.x / (SS / QROWS);
    int s0 = (blockIdx.x % (SS / QROWS)) * QROWS;

    __shared__ float se[QROWS][AA];
    __shared__ float es[QROWS][257];

    int tid = threadIdx.x;
    for (int i = tid; i < QROWS * AA; i += 256)
        se[i / AA][i % AA] = emb[((size_t)(n * SS + s0)) * AA + i];
    __syncthreads();

    int sy = tid >> 5;
    int dx = tid & 31;

    float acc[4][8];
#pragma unroll
    for (int j = 0; j < 8; ++j) {
        float b = bqk[j * 32 + dx];
#pragma unroll
        for (int i = 0; i < 4; ++i) acc[i][j] = b;
    }
#pragma unroll 2
    for (int a = 0; a < AA; ++a) {
        float w[8];
#pragma unroll
        for (int j = 0; j < 8; ++j) w[j] = Wqk[a * DD + j * 32 + dx];
        float sv0 = se[sy * 4 + 0][a], sv1 = se[sy * 4 + 1][a];
        float sv2 = se[sy * 4 + 2][a], sv3 = se[sy * 4 + 3][a];
#pragma unroll
        for (int j = 0; j < 8; ++j) {
            acc[0][j] = fmaf(sv0, w[j], acc[0][j]);
            acc[1][j] = fmaf(sv1, w[j], acc[1][j]);
            acc[2][j] = fmaf(sv2, w[j], acc[2][j]);
            acc[3][j] = fmaf(sv3, w[j], acc[3][j]);
        }
    }

#pragma unroll
    for (int i = 0; i < 4; ++i) {
        float loc = 0.0f;
#pragma unroll
        for (int j = 0; j < 8; ++j) { acc[i][j] = expf(acc[i][j]); loc += acc[i][j]; }
#pragma unroll
        for (int off = 16; off > 0; off >>= 1) loc += __shfl_xor_sync(0xffffffff, loc, off);
        float inv = 1.0f / loc;
        int s = s0 + sy * 4 + i;
#pragma unroll
        for (int j = 0; j < 8; ++j) {
            size_t idx = ((size_t)(n * SS + s)) * DD + j * 32 + dx;
            __half h, l;
            hsplit(acc[i][j] * inv, h, l);
            g_qh[idx] = h;
            g_ql[idx] = l;
            es[sy * 4 + i][j * 32 + dx] = acc[i][j];
        }
    }
    __syncthreads();

    int dq = tid >> 3;
    int sq = (tid & 7) * 4;
#pragma unroll
    for (int pass = 0; pass < 8; ++pass) {
        int d = pass * 32 + dq;
        float v0 = es[sq + 0][d], v1 = es[sq + 1][d], v2 = es[sq + 2][d], v3 = es[sq + 3][d];
        __half h0, l0, h1, l1, h2, l2, h3, l3;
        hsplit(v0, h0, l0); hsplit(v1, h1, l1); hsplit(v2, h2, l2); hsplit(v3, h3, l3);
        size_t base = ((size_t)n * DD + d) * SS + s0 + sq;
        __half2 a = __halves2half2(h0, h1), b = __halves2half2(h2, h3);
        uint2 uh; uh.x = *(uint32_t*)&a; uh.y = *(uint32_t*)&b;
        *(uint2*)&g_ETh[base] = uh;
        __half2 c = __halves2half2(l0, l1), dl = __halves2half2(l2, l3);
        uint2 ul; ul.x = *(uint32_t*)&c; ul.y = *(uint32_t*)&dl;
        *(uint2*)&g_ETl[base] = ul;
    }
}

__global__ void colsum_kernel()
{
    int r = blockIdx.x * 8 + (threadIdx.x >> 5);
    int l = threadIdx.x & 31;
    const uint4* ph = (const uint4*)(g_ETh + (size_t)r * SS);
    const uint4* pl = (const uint4*)(g_ETl + (size_t)r * SS);
    float s = 0.0f;
#pragma unroll
    for (int c = 0; c < 2; ++c) {
        uint4 a = ph[l + c * 32];
        uint4 b = pl[l + c * 32];
        const __half2* pa = (const __half2*)&a;
        const __half2* pb = (const __half2*)&b;
#pragma unroll
        for (int j = 0; j < 4; ++j) {
            float2 fa = __half22float2(pa[j]);
            float2 fb = __half22float2(pb[j]);
            s += fa.x + fa.y + fb.x + fb.y;
        }
    }
#pragma unroll
    for (int off = 16; off > 0; off >>= 1) s += __shfl_xor_sync(0xffffffff, s, off);
    if (l == 0) g_cs[r] = s;
}

// ---------------- warp-MMA fp16 2-term-split batched GEMM --------------------
// 3-stage cp.async ring, wait_group 1. A = pre-split hi/lo fp16 planes.
// B: fp32 (in-kernel convert, hi only) or fp16 hi plane (cp.async).
// OMODE: 0 = fp32 out + bias; 1 = half hi/lo planes + row scale; 2 = half hi.
#define A_STR 80
#define B_STR 272
#define SM_AH 0
#define SM_AL 10240
#define SM_BH 20480
#define SM_STAGE 29184
#define SM_PIPE (3 * SM_STAGE)

template<bool BF32, int OMODE>
__global__ __launch_bounds__(256, 2)
void gemm_mma(const __half* __restrict__ Ahg, const __half* __restrict__ Alg,
              const void* __restrict__ Bg,
              void* __restrict__ Cg, void* __restrict__ C2g,
              int K, int ldb, int ldc,
              long aStride, int aMod, long bStride, int bMod, long cStride,
              const float* __restrict__ scaleBase, int scaleMod,
              const float* __restrict__ bias)
{
    extern __shared__ __align__(16) char smem[];

    int z = blockIdx.z;
    const __half* Ah = Ahg + (long)(aMod ? (z % aMod) : z) * aStride;
    const __half* Al = Alg + (long)(aMod ? (z % aMod) : z) * aStride;
    int m0 = blockIdx.y * 128, n0 = blockIdx.x * 128;

    int tid = threadIdx.x, lane = tid & 31, wid = tid >> 5;
    int wm = wid >> 1, wn = wid & 1;

    uint32_t sb = smem_u32(smem);

    int arow = tid >> 1;
    int au = (tid & 1) * 2;
    const __half* aSrcH = Ah + (size_t)(m0 + arow) * K + au * 8;
    const __half* aSrcL = Al + (size_t)(m0 + arow) * K + au * 8;
    uint32_t aDstH = sb + SM_AH + arow * A_STR + au * 16;
    uint32_t aDstL = sb + SM_AL + arow * A_STR + au * 16;

    int brow, bu = 0, bnb = 0;
    const __half* bSrcH = nullptr;
    const float* bPtr = nullptr;
    uint32_t bDst = 0, bOffH = 0;
    if (BF32) {
        brow = tid >> 3; bnb = (tid & 7) * 16;
        bPtr = (const float*)Bg + (long)(bMod ? (z % bMod) : z) * bStride
             + (long)brow * ldb + n0 + bnb;
        bOffH = SM_BH + brow * B_STR + bnb * 2;
    } else {
        brow = tid >> 3; bu = (tid & 7) * 2;
        bSrcH = (const __half*)Bg + (long)(bMod ? (z % bMod) : z) * bStride
              + (size_t)brow * ldb + n0 + bu * 8;
        bDst = sb + SM_BH + brow * B_STR + bu * 16;
    }

    uint32_t aFH[2], aFL[2], bFH[4];
#pragma unroll
    for (int t = 0; t < 2; ++t) {
        uint32_t off = (uint32_t)((wm * 32 + t * 16 + (lane & 15)) * A_STR + (lane >> 4) * 16);
        aFH[t] = SM_AH + off;
        aFL[t] = SM_AL + off;
    }
#pragma unroll
    for (int p = 0; p < 4; ++p) {
        uint32_t off = (uint32_t)((lane & 15) * B_STR + (wn * 64 + p * 16 + (lane >> 4) * 8) * 2);
        bFH[p] = SM_BH + off;
    }

    float acc[2][8][4];
#pragma unroll
    for (int t = 0; t < 2; ++t)
#pragma unroll
        for (int nt = 0; nt < 8; ++nt)
#pragma unroll
            for (int j = 0; j < 4; ++j) acc[t][nt][j] = 0.0f;

    auto cpAsyncLoad = [&](int kc, uint32_t bufOff) {
        const __half* sh = aSrcH + kc * 32;
        const __half* sl = aSrcL + kc * 32;
        CP16(aDstH + bufOff, sh);
        CP16(aDstH + bufOff + 16, sh + 8);
        CP16(aDstL + bufOff, sl);
        CP16(aDstL + bufOff + 16, sl + 8);
        if (!BF32) {
            const __half* sbp = bSrcH + (size_t)kc * 32 * ldb;
            CP16(bDst + bufOff, sbp);
            CP16(bDst + bufOff + 16, sbp + 8);
        }
    };
    auto bConvStore = [&](int kc, uint32_t bufOff) {
        const float* bp = bPtr + (size_t)kc * 32 * ldb;
        float4 vb0 = *(const float4*)(bp);
        float4 vb1 = *(const float4*)(bp + 4);
        float4 vb2 = *(const float4*)(bp + 8);
        float4 vb3 = *(const float4*)(bp + 12);
        *(uint4*)(smem + bufOff + bOffH) = make_uint4(
            pack2h(vb0.x, vb0.y), pack2h(vb0.z, vb0.w),
            pack2h(vb1.x, vb1.y), pack2h(vb1.z, vb1.w));
        *(uint4*)(smem + bufOff + bOffH + 16) = make_uint4(
            pack2h(vb2.x, vb2.y), pack2h(vb2.z, vb2.w),
            pack2h(vb3.x, vb3.y), pack2h(vb3.z, vb3.w));
    };
    auto mmaStep = [&](int kk, uint32_t bufOff) {
        uint32_t ah[2][4], al[2][4], bf[4][4];
#pragma unroll
        for (int t = 0; t < 2; ++t) {
            ldsm4(ah[t], sb + bufOff + aFH[t] + kk * 32);
            ldsm4(al[t], sb + bufOff + aFL[t] + kk * 32);
        }
#pragma unroll
        for (int p = 0; p < 4; ++p) ldsm4t(bf[p], sb + bufOff + bFH[p] + kk * 16 * B_STR);
#pragma unroll
        for (int t = 0; t < 2; ++t)
#pragma unroll
            for (int nt = 0; nt < 8; ++nt)
                mma16816(acc[t][nt], ah[t], &bf[nt >> 1][(nt & 1) * 2]);
#pragma unroll
        for (int t = 0; t < 2; ++t)
#pragma unroll
            for (int nt = 0; nt < 8; ++nt)
                mma16816(acc[t][nt], al[t], &bf[nt >> 1][(nt & 1) * 2]);
    };

    int KT = K / 32;

    // prologue: stage 0 and 1 loads in flight; B-conv for stage 0 done.
    cpAsyncLoad(0, 0);
    CP_COMMIT();
    cpAsyncLoad(1, SM_STAGE);
    CP_COMMIT();
    if (BF32) bConvStore(0, 0);

    int cur = 0;
    for (int kc = 0; kc < KT; ++kc) {
        uint32_t curOff = (uint32_t)cur * SM_STAGE;
        CP_WAIT1();              // group kc complete (<=1 newer group pending)
        __syncthreads();         // publishes cp.async data + conv STS; frees stage (kc-1)%3
        int pf = kc + 2;
        if (pf < KT) {
            int pfs = pf - 3 * (pf / 3);
            cpAsyncLoad(pf, (uint32_t)pfs * SM_STAGE);
            CP_COMMIT();
        }
        mmaStep(0, curOff);
        if (BF32 && kc + 1 < KT) {
            int ns = (cur + 1 == 3) ? 0 : cur + 1;
            bConvStore(kc + 1, (uint32_t)ns * SM_STAGE);
        }
        mmaStep(1, curOff);
        cur = (cur + 1 == 3) ? 0 : cur + 1;
    }

    // ---- epilogue ----
    const float* sp = (OMODE == 1)
        ? scaleBase + (long)(scaleMod ? (z % scaleMod) : z) * DD : nullptr;
#pragma unroll
    for (int t = 0; t < 2; ++t) {
        int row = m0 + wm * 32 + t * 16 + (lane >> 2);
        float s0 = 1.0f, s1 = 1.0f;
        if (OMODE == 1) { s0 = 1.0f / sp[row]; s1 = 1.0f / sp[row + 8]; }
#pragma unroll
        for (int nt = 0; nt < 8; ++nt) {
            int col = n0 + wn * 64 + nt * 8 + (lane & 3) * 2;
            float v0 = acc[t][nt][0] * s0, v1 = acc[t][nt][1] * s0;
            float v2 = acc[t][nt][2] * s1, v3 = acc[t][nt][3] * s1;
            if (OMODE == 0) {
                float* C = (float*)Cg + (long)z * cStride;
                float2 bb = *(const float2*)(bias + col);
                *(float2*)&C[(long)row * ldc + col] = make_float2(v0 + bb.x, v1 + bb.y);
                *(float2*)&C[(long)(row + 8) * ldc + col] = make_float2(v2 + bb.x, v3 + bb.y);
            } else if (OMODE == 1) {
                __half* Ch = (__half*)Cg + (long)z * cStride;
                __half* Cl = (__half*)C2g + (long)z * cStride;
                __half h0, l0, h1, l1;
                hsplit(v0, h0, l0); hsplit(v1, h1, l1);
                *(__half2*)&Ch[(long)row * ldc + col] = __halves2half2(h0, h1);
                *(__half2*)&Cl[(long)row * ldc + col] = __halves2half2(l0, l1);
                hsplit(v2, h0, l0); hsplit(v3, h1, l1);
                *(__half2*)&Ch[(long)(row + 8) * ldc + col] = __halves2half2(h0, h1);
                *(__half2*)&Cl[(long)(row + 8) * ldc + col] = __halves2half2(l0, l1);
            } else {
                __half* Ch = (__half*)Cg + (long)z * cStride;
                *(__half2*)&Ch[(long)row * ldc + col] =
                    __halves2half2(__float2half_rn(v0), __float2half_rn(v1));
                *(__half2*)&Ch[(long)(row + 8) * ldc + col] =
                    __halves2half2(__float2half_rn(v2), __float2half_rn(v3));
            }
        }
    }
}

// ---------------- launch -----------------------------------------------------
extern "C" void kernel_launch(void* const* d_in, const int* in_sizes, int n_in,
                              void* d_out, int out_size)
{
    const float* value = (const float*)d_in[0];
    const float* emb   = (const float*)d_in[1];
    const float* Wqk   = (const float*)d_in[2];
    const float* bqk   = (const float*)d_in[3];
    const float* Wv    = (const float*)d_in[4];
    const float* bv    = (const float*)d_in[5];
    float* out = (float*)d_out;

    void *pqh, *pql, *pETh, *pETl, *pcs, *pkvh, *pkvl, *pPh;
    cudaGetSymbolAddress(&pqh, g_qh);
    cudaGetSymbolAddress(&pql, g_ql);
    cudaGetSymbolAddress(&pETh, g_ETh);
    cudaGetSymbolAddress(&pETl, g_ETl);
    cudaGetSymbolAddress(&pcs, g_cs);
    cudaGetSymbolAddress(&pkvh, g_kvh);
    cudaGetSymbolAddress(&pkvl, g_kvl);
    cudaGetSymbolAddress(&pPh, g_Ph);

    static int smemSet = 0;
    if (!smemSet) {
        cudaFuncSetAttribute(gemm_mma<true, 1>, cudaFuncAttributeMaxDynamicSharedMemorySize, SM_PIPE);
        cudaFuncSetAttribute(gemm_mma<true, 2>, cudaFuncAttributeMaxDynamicSharedMemorySize, SM_PIPE);
        cudaFuncSetAttribute(gemm_mma<false, 0>, cudaFuncAttributeMaxDynamicSharedMemorySize, SM_PIPE);
        smemSet = 1;
    }

    qk_kernel<<<NN * (SS / QROWS), 256>>>(emb, Wqk, bqk);
    colsum_kernel<<<NN * DD / 8, 256>>>();

    // GEMM1: kv = (ET @ value) / colsum   -> kv hi/lo planes
    gemm_mma<true, 1><<<dim3(2, 2, BB * NN), 256, SM_PIPE>>>(
        (const __half*)pETh, (const __half*)pETl, value,
        pkvh, pkvl,
        SS, DD, DD,
        (long)DD * SS, NN,
        (long)SS * DD, 0,
        (long)DD * DD,
        (const float*)pcs, NN, nullptr);

    // GEMM2: P = kv @ Wv   -> P hi plane only
    gemm_mma<true, 2><<<dim3(2, 2, BB * NN), 256, SM_PIPE>>>(
        (const __half*)pkvh, (const __half*)pkvl, Wv,
        pPh, nullptr,
        DD, DD, DD,
        (long)DD * DD, 0,
        0L, 0,
        (long)DD * DD,
        nullptr, 0, nullptr);

    // GEMM3: out = q @ P + bv   (fp32 out)
    gemm_mma<false, 0><<<dim3(2, 4, BB * NN), 256, SM_PIPE>>>(
        (const __half*)pqh, (const __half*)pql, pPh,
        out, nullptr,
        DD, DD, DD,
        (long)SS * DD, NN,
        (long)DD * DD, 0,
        (long)SS * DD,
        nullptr, 0, bv);
}

// round 13
// speedup vs baseline: 3.1271x; 1.1840x over previous
#include <cuda_runtime.h>
#include <cuda_fp16.h>
#include <cstdint>
#include <math.h>

#define BB 32
#define NN 12
#define SS 512
#define DD 256
#define AA 96

// ---------------- scratch (device globals, fp16 planes) ----------------------
static __device__ __align__(16) __half g_qh[NN * SS * DD];
static __device__ __align__(16) __half g_ETh[NN * DD * SS];
static __device__ __align__(16) __half g_ETl[NN * DD * SS];
static __device__ float g_cs[NN * DD];
static __device__ __align__(16) __half g_kvh[(size_t)BB * NN * DD * DD];
static __device__ __align__(16) __half g_Ph[(size_t)BB * NN * DD * DD];

// ---------------- helpers ----------------------------------------------------
__device__ __forceinline__ uint32_t smem_u32(const void* p) {
    uint32_t a;
    asm("{ .reg .u64 t; cvta.to.shared.u64 t, %1; cvt.u32.u64 %0, t; }" : "=r"(a) : "l"(p));
    return a;
}
__device__ __forceinline__ void ldsm4(uint32_t* r, uint32_t a) {
    asm volatile("ldmatrix.sync.aligned.m8n8.x4.shared.b16 {%0,%1,%2,%3}, [%4];"
                 : "=r"(r[0]), "=r"(r[1]), "=r"(r[2]), "=r"(r[3]) : "r"(a));
}
__device__ __forceinline__ void ldsm4t(uint32_t* r, uint32_t a) {
    asm volatile("ldmatrix.sync.aligned.m8n8.x4.trans.shared.b16 {%0,%1,%2,%3}, [%4];"
                 : "=r"(r[0]), "=r"(r[1]), "=r"(r[2]), "=r"(r[3]) : "r"(a));
}
__device__ __forceinline__ void mma16816(float* c, const uint32_t* a, const uint32_t* b) {
    asm volatile("mma.sync.aligned.m16n8k16.row.col.f32.f16.f16.f32 "
                 "{%0,%1,%2,%3}, {%4,%5,%6,%7}, {%8,%9}, {%0,%1,%2,%3};"
                 : "+f"(c[0]), "+f"(c[1]), "+f"(c[2]), "+f"(c[3])
                 : "r"(a[0]), "r"(a[1]), "r"(a[2]), "r"(a[3]), "r"(b[0]), "r"(b[1]));
}
__device__ __forceinline__ void hsplit(float x, __half& h, __half& l) {
    h = __float2half_rn(x);
    l = __float2half_rn(x - __half2float(h));
}
__device__ __forceinline__ uint32_t pack2h(float x, float y) {
    __half2 hv; hv.x = __float2half_rn(x); hv.y = __float2half_rn(y);
    return *(uint32_t*)&hv;
}
#define CP16(dst, src) \
    asm volatile("cp.async.cg.shared.global [%0], [%1], 16;" :: "r"(dst), "l"(src))
#define CP_COMMIT() asm volatile("cp.async.commit_group;" ::: "memory")
#define CP_WAIT1()  asm volatile("cp.async.wait_group 1;" ::: "memory")

// ---------------- qk kernel: writes q hi plane + ET hi/lo planes --------------
#define QROWS 32
__global__ __launch_bounds__(256)
void qk_kernel(const float* __restrict__ emb,
               const float* __restrict__ Wqk,
               const float* __restrict__ bqk)
{
    int n = blockIdx.x / (SS / QROWS);
    int s0 = (blockIdx.x % (SS / QROWS)) * QROWS;

    __shared__ float se[QROWS][AA];
    __shared__ float es[QROWS][257];

    int tid = threadIdx.x;
    for (int i = tid; i < QROWS * AA; i += 256)
        se[i / AA][i % AA] = emb[((size_t)(n * SS + s0)) * AA + i];
    __syncthreads();

    int sy = tid >> 5;
    int dx = tid & 31;

    float acc[4][8];
#pragma unroll
    for (int j = 0; j < 8; ++j) {
        float b = bqk[j * 32 + dx];
#pragma unroll
        for (int i = 0; i < 4; ++i) acc[i][j] = b;
    }
#pragma unroll 2
    for (int a = 0; a < AA; ++a) {
        float w[8];
#pragma unroll
        for (int j = 0; j < 8; ++j) w[j] = Wqk[a * DD + j * 32 + dx];
        float sv0 = se[sy * 4 + 0][a], sv1 = se[sy * 4 + 1][a];
        float sv2 = se[sy * 4 + 2][a], sv3 = se[sy * 4 + 3][a];
#pragma unroll
        for (int j = 0; j < 8; ++j) {
            acc[0][j] = fmaf(sv0, w[j], acc[0][j]);
            acc[1][j] = fmaf(sv1, w[j], acc[1][j]);
            acc[2][j] = fmaf(sv2, w[j], acc[2][j]);
            acc[3][j] = fmaf(sv3, w[j], acc[3][j]);
        }
    }

#pragma unroll
    for (int i = 0; i < 4; ++i) {
        float loc = 0.0f;
#pragma unroll
        for (int j = 0; j < 8; ++j) { acc[i][j] = expf(acc[i][j]); loc += acc[i][j]; }
#pragma unroll
        for (int off = 16; off > 0; off >>= 1) loc += __shfl_xor_sync(0xffffffff, loc, off);
        float inv = 1.0f / loc;
        int s = s0 + sy * 4 + i;
#pragma unroll
        for (int j = 0; j < 8; ++j) {
            size_t idx = ((size_t)(n * SS + s)) * DD + j * 32 + dx;
            g_qh[idx] = __float2half_rn(acc[i][j] * inv);
            es[sy * 4 + i][j * 32 + dx] = acc[i][j];
        }
    }
    __syncthreads();

    int dq = tid >> 3;
    int sq = (tid & 7) * 4;
#pragma unroll
    for (int pass = 0; pass < 8; ++pass) {
        int d = pass * 32 + dq;
        float v0 = es[sq + 0][d], v1 = es[sq + 1][d], v2 = es[sq + 2][d], v3 = es[sq + 3][d];
        __half h0, l0, h1, l1, h2, l2, h3, l3;
        hsplit(v0, h0, l0); hsplit(v1, h1, l1); hsplit(v2, h2, l2); hsplit(v3, h3, l3);
        size_t base = ((size_t)n * DD + d) * SS + s0 + sq;
        __half2 a = __halves2half2(h0, h1), b = __halves2half2(h2, h3);
        uint2 uh; uh.x = *(uint32_t*)&a; uh.y = *(uint32_t*)&b;
        *(uint2*)&g_ETh[base] = uh;
        __half2 c = __halves2half2(l0, l1), dl = __halves2half2(l2, l3);
        uint2 ul; ul.x = *(uint32_t*)&c; ul.y = *(uint32_t*)&dl;
        *(uint2*)&g_ETl[base] = ul;
    }
}

__global__ void colsum_kernel()
{
    int r = blockIdx.x * 8 + (threadIdx.x >> 5);
    int l = threadIdx.x & 31;
    const uint4* ph = (const uint4*)(g_ETh + (size_t)r * SS);
    const uint4* pl = (const uint4*)(g_ETl + (size_t)r * SS);
    float s = 0.0f;
#pragma unroll
    for (int c = 0; c < 2; ++c) {
        uint4 a = ph[l + c * 32];
        uint4 b = pl[l + c * 32];
        const __half2* pa = (const __half2*)&a;
        const __half2* pb = (const __half2*)&b;
#pragma unroll
        for (int j = 0; j < 4; ++j) {
            float2 fa = __half22float2(pa[j]);
            float2 fb = __half22float2(pb[j]);
            s += fa.x + fa.y + fb.x + fb.y;
        }
    }
#pragma unroll
    for (int off = 16; off > 0; off >>= 1) s += __shfl_xor_sync(0xffffffff, s, off);
    if (l == 0) g_cs[r] = s;
}

// ---------------- warp-MMA fp16 batched GEMM ---------------------------------
// 3-stage cp.async ring, wait_group 1.
// ALO: A has hi+lo planes (2 MMA passes); else single hi pass.
// BF32: B fp32 (in-kernel convert to hi) else fp16 hi plane via cp.async.
// OMODE: 0 = fp32 out + bias; 1 = half hi + row scale; 2 = half hi.
#define A_STR 80
#define B_STR 272
#define SM_AH 0
#define SM_AL 10240
#define SM_BH 20480
#define SM_STAGE 29184
#define SM_PIPE (3 * SM_STAGE)

template<bool BF32, int OMODE, bool ALO>
__global__ __launch_bounds__(256, 2)
void gemm_mma(const __half* __restrict__ Ahg, const __half* __restrict__ Alg,
              const void* __restrict__ Bg,
              void* __restrict__ Cg,
              int K, int ldb, int ldc,
              long aStride, int aMod, long bStride, int bMod, long cStride,
              const float* __restrict__ scaleBase, int scaleMod,
              const float* __restrict__ bias)
{
    extern __shared__ __align__(16) char smem[];

    int z = blockIdx.z;
    const __half* Ah = Ahg + (long)(aMod ? (z % aMod) : z) * aStride;
    const __half* Al = ALO ? (Alg + (long)(aMod ? (z % aMod) : z) * aStride) : nullptr;
    int m0 = blockIdx.y * 128, n0 = blockIdx.x * 128;

    int tid = threadIdx.x, lane = tid & 31, wid = tid >> 5;
    int wm = wid >> 1, wn = wid & 1;

    uint32_t sb = smem_u32(smem);

    int arow = tid >> 1;
    int au = (tid & 1) * 2;
    const __half* aSrcH = Ah + (size_t)(m0 + arow) * K + au * 8;
    const __half* aSrcL = ALO ? (Al + (size_t)(m0 + arow) * K + au * 8) : nullptr;
    uint32_t aDstH = sb + SM_AH + arow * A_STR + au * 16;
    uint32_t aDstL = sb + SM_AL + arow * A_STR + au * 16;

    int brow;
    int bnb = 0, bu = 0;
    const __half* bSrcH = nullptr;
    const float* bPtr = nullptr;
    uint32_t bDst = 0, bOffH = 0;
    if (BF32) {
        brow = tid >> 3; bnb = (tid & 7) * 16;
        bPtr = (const float*)Bg + (long)(bMod ? (z % bMod) : z) * bStride
             + (long)brow * ldb + n0 + bnb;
        bOffH = SM_BH + brow * B_STR + bnb * 2;
    } else {
        brow = tid >> 3; bu = (tid & 7) * 2;
        bSrcH = (const __half*)Bg + (long)(bMod ? (z % bMod) : z) * bStride
              + (size_t)brow * ldb + n0 + bu * 8;
        bDst = sb + SM_BH + brow * B_STR + bu * 16;
    }

    uint32_t aFH[2], aFL[2], bFH[4];
#pragma unroll
    for (int t = 0; t < 2; ++t) {
        uint32_t off = (uint32_t)((wm * 32 + t * 16 + (lane & 15)) * A_STR + (lane >> 4) * 16);
        aFH[t] = SM_AH + off;
        aFL[t] = SM_AL + off;
    }
#pragma unroll
    for (int p = 0; p < 4; ++p) {
        uint32_t off = (uint32_t)((lane & 15) * B_STR + (wn * 64 + p * 16 + (lane >> 4) * 8) * 2);
        bFH[p] = SM_BH + off;
    }

    float acc[2][8][4];
#pragma unroll
    for (int t = 0; t < 2; ++t)
#pragma unroll
        for (int nt = 0; nt < 8; ++nt)
#pragma unroll
            for (int j = 0; j < 4; ++j) acc[t][nt][j] = 0.0f;

    auto cpAsyncLoad = [&](int kc, uint32_t bufOff) {
        const __half* sh = aSrcH + kc * 32;
        CP16(aDstH + bufOff, sh);
        CP16(aDstH + bufOff + 16, sh + 8);
        if (ALO) {
            const __half* sl = aSrcL + kc * 32;
            CP16(aDstL + bufOff, sl);
            CP16(aDstL + bufOff + 16, sl + 8);
        }
        if (!BF32) {
            const __half* sbp = bSrcH + (size_t)kc * 32 * ldb;
            CP16(bDst + bufOff, sbp);
            CP16(bDst + bufOff + 16, sbp + 8);
        }
    };
    auto bConvStore = [&](int kc, uint32_t bufOff) {
        const float* bp = bPtr + (size_t)kc * 32 * ldb;
        float4 vb0 = *(const float4*)(bp);
        float4 vb1 = *(const float4*)(bp + 4);
        float4 vb2 = *(const float4*)(bp + 8);
        float4 vb3 = *(const float4*)(bp + 12);
        *(uint4*)(smem + bufOff + bOffH) = make_uint4(
            pack2h(vb0.x, vb0.y), pack2h(vb0.z, vb0.w),
            pack2h(vb1.x, vb1.y), pack2h(vb1.z, vb1.w));
        *(uint4*)(smem + bufOff + bOffH + 16) = make_uint4(
            pack2h(vb2.x, vb2.y), pack2h(vb2.z, vb2.w),
            pack2h(vb3.x, vb3.y), pack2h(vb3.z, vb3.w));
    };
    auto mmaStep = [&](int kk, uint32_t bufOff) {
        uint32_t ah[2][4], al[2][4], bf[4][4];
#pragma unroll
        for (int t = 0; t < 2; ++t) {
            ldsm4(ah[t], sb + bufOff + aFH[t] + kk * 32);
            if (ALO) ldsm4(al[t], sb + bufOff + aFL[t] + kk * 32);
        }
#pragma unroll
        for (int p = 0; p < 4; ++p) ldsm4t(bf[p], sb + bufOff + bFH[p] + kk * 16 * B_STR);
#pragma unroll
        for (int t = 0; t < 2; ++t)
#pragma unroll
            for (int nt = 0; nt < 8; ++nt)
                mma16816(acc[t][nt], ah[t], &bf[nt >> 1][(nt & 1) * 2]);
        if (ALO) {
#pragma unroll
            for (int t = 0; t < 2; ++t)
#pragma unroll
                for (int nt = 0; nt < 8; ++nt)
                    mma16816(acc[t][nt], al[t], &bf[nt >> 1][(nt & 1) * 2]);
        }
    };

    int KT = K / 32;

    cpAsyncLoad(0, 0);
    CP_COMMIT();
    cpAsyncLoad(1, SM_STAGE);
    CP_COMMIT();
    if (BF32) bConvStore(0, 0);

    int cur = 0;
    for (int kc = 0; kc < KT; ++kc) {
        uint32_t curOff = (uint32_t)cur * SM_STAGE;
        CP_WAIT1();
        __syncthreads();
        int pf = kc + 2;
        if (pf < KT) {
            int pfs = pf - 3 * (pf / 3);
            cpAsyncLoad(pf, (uint32_t)pfs * SM_STAGE);
            CP_COMMIT();
        }
        mmaStep(0, curOff);
        if (BF32 && kc + 1 < KT) {
            int ns = (cur + 1 == 3) ? 0 : cur + 1;
            bConvStore(kc + 1, (uint32_t)ns * SM_STAGE);
        }
        mmaStep(1, curOff);
        cur = (cur + 1 == 3) ? 0 : cur + 1;
    }

    // ---- epilogue ----
    const float* sp = (OMODE == 1)
        ? scaleBase + (long)(scaleMod ? (z % scaleMod) : z) * DD : nullptr;
#pragma unroll
    for (int t = 0; t < 2; ++t) {
        int row = m0 + wm * 32 + t * 16 + (lane >> 2);
        float s0 = 1.0f, s1 = 1.0f;
        if (OMODE == 1) { s0 = 1.0f / sp[row]; s1 = 1.0f / sp[row + 8]; }
#pragma unroll
        for (int nt = 0; nt < 8; ++nt) {
            int col = n0 + wn * 64 + nt * 8 + (lane & 3) * 2;
            float v0 = acc[t][nt][0] * s0, v1 = acc[t][nt][1] * s0;
            float v2 = acc[t][nt][2] * s1, v3 = acc[t][nt][3] * s1;
            if (OMODE == 0) {
                float* C = (float*)Cg + (long)z * cStride;
                float2 bb = *(const float2*)(bias + col);
                *(float2*)&C[(long)row * ldc + col] = make_float2(v0 + bb.x, v1 + bb.y);
                *(float2*)&C[(long)(row + 8) * ldc + col] = make_float2(v2 + bb.x, v3 + bb.y);
            } else {
                __half* Ch = (__half*)Cg + (long)z * cStride;
                *(__half2*)&Ch[(long)row * ldc + col] =
                    __halves2half2(__float2half_rn(v0), __float2half_rn(v1));
                *(__half2*)&Ch[(long)(row + 8) * ldc + col] =
                    __halves2half2(__float2half_rn(v2), __float2half_rn(v3));
            }
        }
    }
}

// ---------------- launch -----------------------------------------------------
extern "C" void kernel_launch(void* const* d_in, const int* in_sizes, int n_in,
                              void* d_out, int out_size)
{
    const float* value = (const float*)d_in[0];
    const float* emb   = (const float*)d_in[1];
    const float* Wqk   = (const float*)d_in[2];
    const float* bqk   = (const float*)d_in[3];
    const float* Wv    = (const float*)d_in[4];
    const float* bv    = (const float*)d_in[5];
    float* out = (float*)d_out;

    void *pqh, *pETh, *pETl, *pcs, *pkvh, *pPh;
    cudaGetSymbolAddress(&pqh, g_qh);
    cudaGetSymbolAddress(&pETh, g_ETh);
    cudaGetSymbolAddress(&pETl, g_ETl);
    cudaGetSymbolAddress(&pcs, g_cs);
    cudaGetSymbolAddress(&pkvh, g_kvh);
    cudaGetSymbolAddress(&pPh, g_Ph);

    static int smemSet = 0;
    if (!smemSet) {
        cudaFuncSetAttribute(gemm_mma<true, 1, true>,  cudaFuncAttributeMaxDynamicSharedMemorySize, SM_PIPE);
        cudaFuncSetAttribute(gemm_mma<true, 2, false>, cudaFuncAttributeMaxDynamicSharedMemorySize, SM_PIPE);
        cudaFuncSetAttribute(gemm_mma<false, 0, false>, cudaFuncAttributeMaxDynamicSharedMemorySize, SM_PIPE);
        smemSet = 1;
    }

    qk_kernel<<<NN * (SS / QROWS), 256>>>(emb, Wqk, bqk);
    colsum_kernel<<<NN * DD / 8, 256>>>();

    // GEMM1: kv = (ET @ value) / colsum  -> kv hi plane (2-pass A: ETh+ETl)
    gemm_mma<true, 1, true><<<dim3(2, 2, BB * NN), 256, SM_PIPE>>>(
        (const __half*)pETh, (const __half*)pETl, value,
        pkvh,
        SS, DD, DD,
        (long)DD * SS, NN,
        (long)SS * DD, 0,
        (long)DD * DD,
        (const float*)pcs, NN, nullptr);

    // GEMM2: P = kv @ Wv  -> P hi plane (single-pass A)
    gemm_mma<true, 2, false><<<dim3(2, 2, BB * NN), 256, SM_PIPE>>>(
        (const __half*)pkvh, nullptr, Wv,
        pPh,
        DD, DD, DD,
        (long)DD * DD, 0,
        0L, 0,
        (long)DD * DD,
        nullptr, 0, nullptr);

    // GEMM3: out = q @ P + bv  (single-pass A, fp32 out)
    gemm_mma<false, 0, false><<<dim3(2, 4, BB * NN), 256, SM_PIPE>>>(
        (const __half*)pqh, nullptr, pPh,
        out,
        DD, DD, DD,
        (long)SS * DD, NN,
        (long)DD * DD, 0,
        (long)SS * DD,
        nullptr, 0, bv);
}